// round 8
// baseline (speedup 1.0000x reference)
#include <cuda_runtime.h>
#include <cstdint>

typedef unsigned long long ull;

#define NN    50000
#define NE    500000
#define DIM   160
#define HEADS 5
#define MH    50
#define NV4   (DIM/4)      // 40 float4 per row
#define TILE  96           // rows per GEMM tile
#define RPW   6            // rows per warp (16 warps)
#define NB    ((NN + 255) / 256)   // scan blocks
#define NCHUNK ((NN + 31) / 32)
#define HBS   162          // hbuf stride (even -> aligned LDS.64)
#define TBS   52           // tbuf stride
#define W1S   162          // W1t row stride
#define W2S   54           // W2t row stride

// ---------------- scratch (static device globals: allocation-free) ----------
__device__ float g_xl[NN * DIM];
__device__ float g_xr[NN * DIM];
__device__ float g_attn[NN * DIM];
__device__ float g_esc[(size_t)NE * HEADS];    // raw scores, edge order
__device__ int   g_csrc[NE];                   // src node per CSR slot
__device__ int   g_eid[NE];                    // CSR slot -> edge id
__device__ int   g_deg[NN];
__device__ int   g_off[NN];
__device__ int   g_cur[NN];
__device__ int   g_bsum[256];

__device__ __forceinline__ float selu_f(float v) {
    const float sc = 1.0507009873554805f, al = 1.6732632423543772f;
    return v > 0.f ? sc * v : sc * al * (expf(v) - 1.f);
}

#define FFMA2(d, a, b) asm("fma.rn.f32x2 %0, %1, %2, %0;" : "+l"(d) : "l"(a), "l"(b))

__device__ __forceinline__ float unpack_add(ull v) {
    return __uint_as_float((unsigned)v) + __uint_as_float((unsigned)(v >> 32));
}

// ---------------- CSR build ----------------
__global__ void zero_deg_kernel() {
    int i = blockIdx.x * blockDim.x + threadIdx.x;
    if (i < NN) g_deg[i] = 0;
}
__global__ void count_kernel(const int* __restrict__ dst) {
    int e = blockIdx.x * blockDim.x + threadIdx.x;
    if (e < NE) atomicAdd(&g_deg[dst[e]], 1);
}
__global__ void scan1_kernel() {
    __shared__ int wsum[8];
    int tid = threadIdx.x, lane = tid & 31, warp = tid >> 5;
    int i = blockIdx.x * 256 + tid;
    int v = (i < NN) ? g_deg[i] : 0;
    int x = v;
    #pragma unroll
    for (int d = 1; d < 32; d <<= 1) {
        int y = __shfl_up_sync(0xffffffffu, x, d);
        if (lane >= d) x += y;
    }
    if (lane == 31) wsum[warp] = x;
    __syncthreads();
    if (tid == 0) {
        int s = 0;
        #pragma unroll
        for (int j = 0; j < 8; j++) { int t = wsum[j]; wsum[j] = s; s += t; }
        g_bsum[blockIdx.x] = s;
    }
    __syncthreads();
    if (i < NN) g_off[i] = x - v + wsum[warp];
}
__global__ void scan2_kernel() {
    __shared__ int wsum[8];
    int tid = threadIdx.x, lane = tid & 31, warp = tid >> 5;
    int v = (tid < NB) ? g_bsum[tid] : 0;
    int x = v;
    #pragma unroll
    for (int d = 1; d < 32; d <<= 1) {
        int y = __shfl_up_sync(0xffffffffu, x, d);
        if (lane >= d) x += y;
    }
    if (lane == 31) wsum[warp] = x;
    __syncthreads();
    if (tid == 0) {
        int s = 0;
        #pragma unroll
        for (int j = 0; j < 8; j++) { int t = wsum[j]; wsum[j] = s; s += t; }
    }
    __syncthreads();
    if (tid < NB) g_bsum[tid] = x - v + wsum[warp];
}
__global__ void scan3_kernel() {
    int i = blockIdx.x * blockDim.x + threadIdx.x;
    if (i < NN) {
        int o = g_off[i] + g_bsum[i >> 8];
        g_off[i] = o;
        g_cur[i] = o;
    }
}
__global__ void fill_kernel(const int* __restrict__ src, const int* __restrict__ dst) {
    int e = blockIdx.x * blockDim.x + threadIdx.x;
    if (e < NE) {
        int pos = atomicAdd(&g_cur[dst[e]], 1);
        g_eid[pos] = e;
        g_csrc[pos] = src[e];
    }
}

// ---------------- cp.async tile loader: 96 rows x 160 floats ----------------
__device__ __forceinline__ void tile_load_async(float* buf, const float* src_mat,
                                                long row0, long nrows, int tid) {
    unsigned base = (unsigned)__cvta_generic_to_shared(buf);
    #pragma unroll
    for (int it = 0; it < 8; it++) {
        int i = tid + it * 512;                // 3840 float4 total
        if (i < TILE * NV4) {
            int r = i / NV4;
            long row = row0 + r;
            const float4* p = (const float4*)src_mat +
                              (row < nrows ? row * NV4 + (i - r * NV4) : 0);
            int sz = (row < nrows) ? 16 : 0;
            asm volatile("cp.async.cg.shared.global [%0], [%1], 16, %2;\n"
                         :: "r"(base + (unsigned)i * 16u), "l"(p), "r"(sz));
        }
    }
}

// ---- f32x2 GEMM mainloop: 96 rows x 160 cols, K=160, k-step 4, LDS.128 ----
__device__ __forceinline__ void gemm_tile_f2(const float* __restrict__ Wt4,
                                             const float* __restrict__ a_s,
                                             int warp, int lane, ull acc[RPW][5]) {
    #pragma unroll
    for (int r = 0; r < RPW; r++)
        #pragma unroll
        for (int c = 0; c < 5; c++) acc[r][c] = 0ull;
    const float* arow = a_s + warp * RPW * DIM;
    const ulonglong2* wq = (const ulonglong2*)Wt4;
    #pragma unroll 2
    for (int k = 0; k < DIM; k += 4) {
        ulonglong2 xv[RPW];
        #pragma unroll
        for (int r = 0; r < RPW; r++)
            xv[r] = *(const ulonglong2*)(arow + r * DIM + k);   // broadcast LDS.128
        ulonglong2 wv[5];
        int base = (k >> 2) * DIM + lane;
        #pragma unroll
        for (int c = 0; c < 5; c++)
            wv[c] = wq[base + 32 * c];                           // coalesced LDS.128
        #pragma unroll
        for (int r = 0; r < RPW; r++)
            #pragma unroll
            for (int c = 0; c < 5; c++) {
                FFMA2(acc[r][c], xv[r].x, wv[c].x);
                FFMA2(acc[r][c], xv[r].y, wv[c].y);
            }
    }
}

// load W [k][col] row-major -> Wt4 [(k/4)][col][4] packed layout
__device__ __forceinline__ void load_W_t4(float* Wt4, const float* W, int tid, int nthr) {
    for (int i = tid; i < DIM * DIM; i += nthr) {
        int kk = i / DIM, cc = i - kk * DIM;
        Wt4[(((kk >> 2) * DIM) + cc) * 4 + (kk & 3)] = W[i];
    }
}

// ---------------- K: xl = x@Wl+bl, xr = x@Wr+br (grid.y selects) ------------
__global__ __launch_bounds__(512, 1)
void node_transform_kernel(const float* __restrict__ x,
                           const float* __restrict__ Wl, const float* __restrict__ bl,
                           const float* __restrict__ Wr, const float* __restrict__ br) {
    extern __shared__ float sm[];
    float* Wt4  = sm;                   // 160*160 floats (float4-packed)
    float* buf0 = sm + DIM * DIM;       // 96*160
    float* buf1 = buf0 + TILE * DIM;    // 96*160
    const float* W    = blockIdx.y ? Wr : Wl;
    const float* bias = blockIdx.y ? br : bl;
    float* out        = blockIdx.y ? g_xr : g_xl;
    int tid = threadIdx.x, lane = tid & 31, warp = tid >> 5;

    load_W_t4(Wt4, W, tid, 512);
    float bv[5];
    #pragma unroll
    for (int c = 0; c < 5; c++) bv[c] = bias[lane + 32 * c];

    int ntiles = (NN + TILE - 1) / TILE;
    float* cur = buf0; float* nxt = buf1;
    tile_load_async(cur, x, (long)blockIdx.x * TILE, NN, tid);
    asm volatile("cp.async.commit_group;\n");
    for (int t = blockIdx.x; t < ntiles; t += gridDim.x) {
        tile_load_async(nxt, x, (long)(t + gridDim.x) * TILE, NN, tid);
        asm volatile("cp.async.commit_group;\n");
        asm volatile("cp.async.wait_group 1;\n");
        __syncthreads();
        ull acc[RPW][5];
        gemm_tile_f2(Wt4, cur, warp, lane, acc);
        long r0 = (long)t * TILE + warp * RPW;
        #pragma unroll
        for (int r = 0; r < RPW; r++) {
            long gr = r0 + r;
            if (gr < NN) {
                #pragma unroll
                for (int c = 0; c < 5; c++)
                    out[gr * DIM + lane + 32 * c] = unpack_add(acc[r][c]) + bv[c];
            }
        }
        __syncthreads();
        float* tmp = cur; cur = nxt; nxt = tmp;
    }
}

// ------- K: ea = edge_attr@We, fused gather + score (edge-order out) --------
__global__ __launch_bounds__(512, 1)
void edge_score_kernel(const float* __restrict__ edge_attr,
                       const int* __restrict__ src, const int* __restrict__ dst,
                       const float* __restrict__ We, const float* __restrict__ att) {
    extern __shared__ float sm[];
    float* Wt4   = sm;
    float* buf0  = sm + DIM * DIM;
    float* buf1  = buf0 + TILE * DIM;
    float* att_s = buf1 + TILE * DIM;
    int tid = threadIdx.x, lane = tid & 31, warp = tid >> 5;

    load_W_t4(Wt4, We, tid, 512);
    if (tid < DIM) att_s[tid] = att[tid];

    int ntiles = (NE + TILE - 1) / TILE;
    float* cur = buf0; float* nxt = buf1;
    tile_load_async(cur, edge_attr, (long)blockIdx.x * TILE, NE, tid);
    asm volatile("cp.async.commit_group;\n");
    for (int t = blockIdx.x; t < ntiles; t += gridDim.x) {
        tile_load_async(nxt, edge_attr, (long)(t + gridDim.x) * TILE, NE, tid);
        asm volatile("cp.async.commit_group;\n");
        asm volatile("cp.async.wait_group 1;\n");
        __syncthreads();
        ull acc[RPW][5];
        gemm_tile_f2(Wt4, cur, warp, lane, acc);
        int e0 = t * TILE + warp * RPW;
        #pragma unroll
        for (int r = 0; r < RPW; r++) {
            int e = e0 + r;
            if (e < NE) {                      // uniform across warp
                int s = src[e], d = dst[e];
                const float* xlr = g_xl + (long)s * DIM;
                const float* xrr = g_xr + (long)d * DIM;
                #pragma unroll
                for (int c = 0; c < 5; c++) {  // c == head, lane == channel
                    int col = lane + 32 * c;
                    float m = unpack_add(acc[r][c]) + xlr[col] + xrr[col];
                    m = (m > 0.f) ? m : 0.2f * m;         // leaky_relu 0.2
                    float v = m * att_s[col];
                    #pragma unroll
                    for (int off = 16; off; off >>= 1)
                        v += __shfl_xor_sync(0xffffffffu, v, off);
                    if (lane == 0)
                        g_esc[(long)e * HEADS + c] = v;   // raw score, edge order
                }
            }
        }
        __syncthreads();
        float* tmp = cur; cur = nxt; nxt = tmp;
    }
}

// ---- single-pass softmax + aggregate (warp/node, no max: exp(s) directly) --
__global__ __launch_bounds__(256)
void softagg_kernel() {
    int w = (int)(((long)blockIdx.x * blockDim.x + threadIdx.x) >> 5);
    int lane = threadIdx.x & 31;
    if (w >= NN) return;
    long off = g_off[w]; int deg = g_deg[w];
    float a0 = 0.f, a1 = 0.f, a2 = 0.f, a3 = 0.f, a4 = 0.f;
    float s0 = 0.f, s1 = 0.f, s2 = 0.f, s3 = 0.f, s4 = 0.f;
    const int* ep = g_eid + off;
    const int* sp = g_csrc + off;
    #pragma unroll 2
    for (int i = 0; i < deg; i++) {
        long e = ep[i];                              // broadcast
        int s = sp[i];                               // broadcast
        const float* sc = g_esc + e * 5;             // broadcast 20B
        float w0 = expf(sc[0]), w1 = expf(sc[1]), w2 = expf(sc[2]);
        float w3 = expf(sc[3]), w4 = expf(sc[4]);
        s0 += w0; s1 += w1; s2 += w2; s3 += w3; s4 += w4;
        const float* xr = g_xl + (long)s * DIM + lane;
        a0 = fmaf(w0, xr[0],   a0);
        a1 = fmaf(w1, xr[32],  a1);
        a2 = fmaf(w2, xr[64],  a2);
        a3 = fmaf(w3, xr[96],  a3);
        a4 = fmaf(w4, xr[128], a4);
    }
    float* o = g_attn + (long)w * DIM + lane;
    if (deg > 0) {
        o[0]   = a0 / s0;
        o[32]  = a1 / s1;
        o[64]  = a2 / s2;
        o[96]  = a3 / s3;
        o[128] = a4 / s4;
    } else {
        o[0] = 0.f; o[32] = 0.f; o[64] = 0.f; o[96] = 0.f; o[128] = 0.f;
    }
}

// ------- fused tail: LN1 -> MLP(160->50->160) -> LN2, FFMA2 GEMMs ----------
__global__ __launch_bounds__(256, 2)
void tail_kernel(const float* __restrict__ x, const float* __restrict__ bias,
                 const float* __restrict__ g1, const float* __restrict__ bt1,
                 const float* __restrict__ W1, const float* __restrict__ b1,
                 const float* __restrict__ gm, const float* __restrict__ bm,
                 const float* __restrict__ W2, const float* __restrict__ b2,
                 const float* __restrict__ g2, const float* __restrict__ bt2,
                 float* __restrict__ out) {
    extern __shared__ float sm[];
    float* W1t   = sm;                  // 50 x W1S (transposed [c][k])
    float* W2t   = W1t + MH * W1S;      // 160 x W2S (transposed [c][k])
    float* hbuf  = W2t + DIM * W2S;     // 32 x HBS
    float* tbuf  = hbuf + 32 * HBS;     // 32 x TBS
    float* bias_s = tbuf + 32 * TBS;
    float* g1_s  = bias_s + DIM;
    float* bt1_s = g1_s + DIM;
    float* b2_s  = bt1_s + DIM;
    float* g2_s  = b2_s + DIM;
    float* bt2_s = g2_s + DIM;
    float* b1_s  = bt2_s + DIM;
    float* gm_s  = b1_s + MH;
    float* bm_s  = gm_s + MH;
    int tid = threadIdx.x, lane = tid & 31, warp = tid >> 5;

    for (int i = tid; i < DIM * MH; i += 256) {
        int kk = i / MH, cc = i - kk * MH;           // W1[k][c]
        W1t[cc * W1S + kk] = W1[i];
    }
    for (int i = tid; i < MH * DIM; i += 256) {
        int kk = i / DIM, cc = i - kk * DIM;         // W2[k][c]
        W2t[cc * W2S + kk] = W2[i];
    }
    if (tid < DIM) {
        bias_s[tid] = bias[tid]; g1_s[tid] = g1[tid]; bt1_s[tid] = bt1[tid];
        b2_s[tid] = b2[tid]; g2_s[tid] = g2[tid]; bt2_s[tid] = bt2[tid];
    }
    if (tid < MH) { b1_s[tid] = b1[tid]; gm_s[tid] = gm[tid]; bm_s[tid] = bm[tid]; }
    __syncthreads();

    for (int chunk = blockIdx.x; chunk < NCHUNK; chunk += gridDim.x) {
        int n0 = chunk * 32;
        // --- phase A: h = LN(x + attn + bias) -> hbuf (warp per node) ---
        #pragma unroll
        for (int i = 0; i < 4; i++) {
            int nl = warp + 8 * i;
            long n = n0 + nl;
            float v[5];
            if (n < NN) {
                #pragma unroll
                for (int c = 0; c < 5; c++) {
                    int col = lane + 32 * c;
                    v[c] = x[n * DIM + col] + g_attn[n * DIM + col] + bias_s[col];
                }
            } else {
                #pragma unroll
                for (int c = 0; c < 5; c++) v[c] = 0.f;
            }
            float p1 = 0.f, p2 = 0.f;
            #pragma unroll
            for (int c = 0; c < 5; c++) { p1 += v[c]; p2 += v[c] * v[c]; }
            #pragma unroll
            for (int off = 16; off; off >>= 1) {
                p1 += __shfl_xor_sync(0xffffffffu, p1, off);
                p2 += __shfl_xor_sync(0xffffffffu, p2, off);
            }
            float mu = p1 * (1.f / DIM);
            float rstd = rsqrtf(p2 * (1.f / DIM) - mu * mu + 1e-5f);
            #pragma unroll
            for (int c = 0; c < 5; c++) {
                int col = lane + 32 * c;
                hbuf[nl * HBS + col] = (v[c] - mu) * rstd * g1_s[col] + bt1_s[col];
            }
        }
        __syncthreads();
        // --- phase B: t = selu(h@W1 + b1) -> tbuf (FFMA2 over k-pairs) ---
        {
            int cg = lane, ng = warp;
            ull a0[4] = {0ull,0ull,0ull,0ull}, a1[4] = {0ull,0ull,0ull,0ull};
            #pragma unroll 4
            for (int k = 0; k < DIM; k += 2) {
                ull w0 = *(const ull*)(W1t + cg * W1S + k);
                ull w1 = (cg < MH - 32) ? *(const ull*)(W1t + (cg + 32) * W1S + k) : 0ull;
                #pragma unroll
                for (int i = 0; i < 4; i++) {
                    ull hv = *(const ull*)(hbuf + (ng * 4 + i) * HBS + k);
                    FFMA2(a0[i], hv, w0);
                    FFMA2(a1[i], hv, w1);
                }
            }
            #pragma unroll
            for (int i = 0; i < 4; i++) {
                int nl = ng * 4 + i;
                tbuf[nl * TBS + cg] = selu_f(unpack_add(a0[i]) + b1_s[cg]);
                if (cg < MH - 32)
                    tbuf[nl * TBS + cg + 32] = selu_f(unpack_add(a1[i]) + b1_s[cg + 32]);
            }
        }
        __syncthreads();
        // --- LN over 50 (thread per node) ---
        if (tid < 32) {
            float p1 = 0.f, p2 = 0.f;
            for (int k = 0; k < MH; k++) { float t = tbuf[tid * TBS + k]; p1 += t; p2 += t * t; }
            float mu = p1 * (1.f / MH);
            float rstd = rsqrtf(p2 * (1.f / MH) - mu * mu + 1e-5f);
            for (int k = 0; k < MH; k++)
                tbuf[tid * TBS + k] = (tbuf[tid * TBS + k] - mu) * rstd * gm_s[k] + bm_s[k];
        }
        __syncthreads();
        // --- phase C: mlp = u@W2 + b2; out = LN(h + mlp) (FFMA2 over k) ---
        {
            ull acc[4][5];
            #pragma unroll
            for (int i = 0; i < 4; i++)
                #pragma unroll
                for (int c = 0; c < 5; c++) acc[i][c] = 0ull;
            #pragma unroll 5
            for (int k = 0; k < MH; k += 2) {
                ull wv[5];
                #pragma unroll
                for (int c = 0; c < 5; c++)
                    wv[c] = *(const ull*)(W2t + (lane + 32 * c) * W2S + k);
                #pragma unroll
                for (int i = 0; i < 4; i++) {
                    ull uv = *(const ull*)(tbuf + (warp * 4 + i) * TBS + k);
                    #pragma unroll
                    for (int c = 0; c < 5; c++) FFMA2(acc[i][c], uv, wv[c]);
                }
            }
            #pragma unroll
            for (int i = 0; i < 4; i++) {
                int nl = warp * 4 + i;
                long n = n0 + nl;
                float v[5];
                #pragma unroll
                for (int c = 0; c < 5; c++) {
                    int col = lane + 32 * c;
                    v[c] = hbuf[nl * HBS + col] + unpack_add(acc[i][c]) + b2_s[col];
                }
                float p1 = 0.f, p2 = 0.f;
                #pragma unroll
                for (int c = 0; c < 5; c++) { p1 += v[c]; p2 += v[c] * v[c]; }
                #pragma unroll
                for (int off = 16; off; off >>= 1) {
                    p1 += __shfl_xor_sync(0xffffffffu, p1, off);
                    p2 += __shfl_xor_sync(0xffffffffu, p2, off);
                }
                float mu = p1 * (1.f / DIM);
                float rstd = rsqrtf(p2 * (1.f / DIM) - mu * mu + 1e-5f);
                if (n < NN) {
                    #pragma unroll
                    for (int c = 0; c < 5; c++) {
                        int col = lane + 32 * c;
                        out[n * DIM + col] = (v[c] - mu) * rstd * g2_s[col] + bt2_s[col];
                    }
                }
            }
        }
        __syncthreads();
    }
}

// ---------------- launch ----------------
extern "C" void kernel_launch(void* const* d_in, const int* in_sizes, int n_in,
                              void* d_out, int out_size) {
    const float* x         = (const float*)d_in[0];
    const int*   edge_index= (const int*)d_in[1];
    const float* edge_attr = (const float*)d_in[2];
    const float* Wl  = (const float*)d_in[5];
    const float* bl  = (const float*)d_in[6];
    const float* Wr  = (const float*)d_in[7];
    const float* br  = (const float*)d_in[8];
    const float* We  = (const float*)d_in[9];
    const float* att = (const float*)d_in[10];
    const float* bias= (const float*)d_in[11];
    const float* g1  = (const float*)d_in[12];
    const float* bt1 = (const float*)d_in[13];
    const float* W1  = (const float*)d_in[14];
    const float* b1  = (const float*)d_in[15];
    const float* gm  = (const float*)d_in[16];
    const float* bm  = (const float*)d_in[17];
    const float* W2  = (const float*)d_in[18];
    const float* b2  = (const float*)d_in[19];
    const float* g2  = (const float*)d_in[20];
    const float* bt2 = (const float*)d_in[21];
    float* out = (float*)d_out;
    const int* src = edge_index;
    const int* dst = edge_index + NE;

    const int SM_NODE = (DIM * DIM + 2 * TILE * DIM) * (int)sizeof(float);       // 225280
    const int SM_EDGE = (DIM * DIM + 2 * TILE * DIM + DIM) * (int)sizeof(float); // 225920
    const int SM_TAIL = (MH * W1S + DIM * W2S + 32 * HBS + 32 * TBS + 6 * DIM + 3 * MH)
                        * (int)sizeof(float);                                    // ~99 KB
    cudaFuncSetAttribute(node_transform_kernel, cudaFuncAttributeMaxDynamicSharedMemorySize, SM_NODE);
    cudaFuncSetAttribute(edge_score_kernel,     cudaFuncAttributeMaxDynamicSharedMemorySize, SM_EDGE);
    cudaFuncSetAttribute(tail_kernel,           cudaFuncAttributeMaxDynamicSharedMemorySize, SM_TAIL);

    node_transform_kernel<<<dim3(148, 2), 512, SM_NODE>>>(x, Wl, bl, Wr, br); // 0
    zero_deg_kernel<<<(NN + 255) / 256, 256>>>();                             // 1
    count_kernel<<<(NE + 255) / 256, 256>>>(dst);                             // 2
    edge_score_kernel<<<148, 512, SM_EDGE>>>(edge_attr, src, dst, We, att);   // 3 (profiled)
    scan1_kernel<<<NB, 256>>>();                                              // 4
    scan2_kernel<<<1, 256>>>();                                               // 5
    scan3_kernel<<<(NN + 255) / 256, 256>>>();                                // 6
    fill_kernel<<<(NE + 255) / 256, 256>>>(src, dst);                         // 7
    softagg_kernel<<<(NN + 7) / 8, 256>>>();                                  // 8
    tail_kernel<<<296, 256, SM_TAIL>>>(x, bias, g1, bt1, W1, b1, gm, bm,
                                       W2, b2, g2, bt2, out);                 // 9
}

// round 11
// speedup vs baseline: 1.5104x; 1.5104x over previous
#include <cuda_runtime.h>
#include <cstdint>

typedef unsigned long long ull;

#define NN    50000
#define NE    500000
#define DIM   160
#define HEADS 5
#define MH    50
#define NV4   (DIM/4)      // 40 float4 per row
#define TILE  96           // rows per GEMM tile
#define RPW   6            // rows per warp (16 warps)
#define NB    ((NN + 255) / 256)   // scan blocks
#define NCHUNK ((NN + 31) / 32)
#define HBS   162          // hbuf stride
#define TBS   52           // tbuf stride
#define W1S   162          // W1t row stride
#define W2S   54           // W2t row stride

// ---------------- scratch (static device globals: allocation-free) ----------
__device__ float g_xl[NN * DIM];
__device__ float g_xr[NN * DIM];
__device__ float g_attn[NN * DIM];
__device__ float g_ea[(size_t)NE * DIM];   // edge GEMM output, CSR order (320 MB)
__device__ int   g_csrc[NE];               // src node per CSR slot
__device__ int   g_pos[NE];                // edge id -> CSR slot
__device__ int   g_deg[NN];
__device__ int   g_off[NN];
__device__ int   g_cur[NN];
__device__ int   g_bsum[256];

__device__ __forceinline__ float selu_f(float v) {
    const float sc = 1.0507009873554805f, al = 1.6732632423543772f;
    return v > 0.f ? sc * v : sc * al * (expf(v) - 1.f);
}

#define FFMA2(d, a, b) asm("fma.rn.f32x2 %0, %1, %2, %0;" : "+l"(d) : "l"(a), "l"(b))

__device__ __forceinline__ float unpack_add(ull v) {
    return __uint_as_float((unsigned)v) + __uint_as_float((unsigned)(v >> 32));
}

// ---------------- CSR build ----------------
__global__ void zero_deg_kernel() {
    int i = blockIdx.x * blockDim.x + threadIdx.x;
    if (i < NN) g_deg[i] = 0;
}
__global__ void count_kernel(const int* __restrict__ dst) {
    int e = blockIdx.x * blockDim.x + threadIdx.x;
    if (e < NE) atomicAdd(&g_deg[dst[e]], 1);
}
__global__ void scan1_kernel() {
    __shared__ int wsum[8];
    int tid = threadIdx.x, lane = tid & 31, warp = tid >> 5;
    int i = blockIdx.x * 256 + tid;
    int v = (i < NN) ? g_deg[i] : 0;
    int x = v;
    #pragma unroll
    for (int d = 1; d < 32; d <<= 1) {
        int y = __shfl_up_sync(0xffffffffu, x, d);
        if (lane >= d) x += y;
    }
    if (lane == 31) wsum[warp] = x;
    __syncthreads();
    if (tid == 0) {
        int s = 0;
        #pragma unroll
        for (int j = 0; j < 8; j++) { int t = wsum[j]; wsum[j] = s; s += t; }
        g_bsum[blockIdx.x] = s;
    }
    __syncthreads();
    if (i < NN) g_off[i] = x - v + wsum[warp];
}
__global__ void scan2_kernel() {
    __shared__ int wsum[8];
    int tid = threadIdx.x, lane = tid & 31, warp = tid >> 5;
    int v = (tid < NB) ? g_bsum[tid] : 0;
    int x = v;
    #pragma unroll
    for (int d = 1; d < 32; d <<= 1) {
        int y = __shfl_up_sync(0xffffffffu, x, d);
        if (lane >= d) x += y;
    }
    if (lane == 31) wsum[warp] = x;
    __syncthreads();
    if (tid == 0) {
        int s = 0;
        #pragma unroll
        for (int j = 0; j < 8; j++) { int t = wsum[j]; wsum[j] = s; s += t; }
    }
    __syncthreads();
    if (tid < NB) g_bsum[tid] = x - v + wsum[warp];
}
__global__ void scan3_kernel() {
    int i = blockIdx.x * blockDim.x + threadIdx.x;
    if (i < NN) {
        int o = g_off[i] + g_bsum[i >> 8];
        g_off[i] = o;
        g_cur[i] = o;
    }
}
__global__ void fill_kernel(const int* __restrict__ src, const int* __restrict__ dst) {
    int e = blockIdx.x * blockDim.x + threadIdx.x;
    if (e < NE) {
        int pos = atomicAdd(&g_cur[dst[e]], 1);
        g_pos[e] = pos;
        g_csrc[pos] = src[e];
    }
}

// ---------------- cp.async tile loader: 96 rows x 160 floats ----------------
__device__ __forceinline__ void tile_load_async(float* buf, const float* src_mat,
                                                long row0, long nrows, int tid) {
    unsigned base = (unsigned)__cvta_generic_to_shared(buf);
    #pragma unroll
    for (int it = 0; it < 8; it++) {
        int i = tid + it * 512;                // 3840 float4 total
        if (i < TILE * NV4) {
            int r = i / NV4;
            long row = row0 + r;
            const float4* p = (const float4*)src_mat +
                              (row < nrows ? row * NV4 + (i - r * NV4) : 0);
            int sz = (row < nrows) ? 16 : 0;
            asm volatile("cp.async.cg.shared.global [%0], [%1], 16, %2;\n"
                         :: "r"(base + (unsigned)i * 16u), "l"(p), "r"(sz));
        }
    }
}

// ---- f32x2 GEMM mainloop: 96 rows x 160 cols, K=160, k-step 4, LDS.128 ----
__device__ __forceinline__ void gemm_tile_f2(const float* __restrict__ Wt4,
                                             const float* __restrict__ a_s,
                                             int warp, int lane, ull acc[RPW][5]) {
    #pragma unroll
    for (int r = 0; r < RPW; r++)
        #pragma unroll
        for (int c = 0; c < 5; c++) acc[r][c] = 0ull;
    const float* arow = a_s + warp * RPW * DIM;
    const ulonglong2* wq = (const ulonglong2*)Wt4;
    #pragma unroll 2
    for (int k = 0; k < DIM; k += 4) {
        ulonglong2 xv[RPW];
        #pragma unroll
        for (int r = 0; r < RPW; r++)
            xv[r] = *(const ulonglong2*)(arow + r * DIM + k);   // broadcast LDS.128
        ulonglong2 wv[5];
        int base = (k >> 2) * DIM + lane;
        #pragma unroll
        for (int c = 0; c < 5; c++)
            wv[c] = wq[base + 32 * c];                           // coalesced LDS.128
        #pragma unroll
        for (int r = 0; r < RPW; r++)
            #pragma unroll
            for (int c = 0; c < 5; c++) {
                FFMA2(acc[r][c], xv[r].x, wv[c].x);
                FFMA2(acc[r][c], xv[r].y, wv[c].y);
            }
    }
}

// load W [k][col] row-major -> Wt4 [(k/4)][col][4] packed layout
__device__ __forceinline__ void load_W_t4(float* Wt4, const float* W, int tid, int nthr) {
    for (int i = tid; i < DIM * DIM; i += nthr) {
        int kk = i / DIM, cc = i - kk * DIM;
        Wt4[(((kk >> 2) * DIM) + cc) * 4 + (kk & 3)] = W[i];
    }
}

// ---------------- K: xl = x@Wl+bl, xr = x@Wr+br (grid.y selects) ------------
__global__ __launch_bounds__(512, 1)
void node_transform_kernel(const float* __restrict__ x,
                           const float* __restrict__ Wl, const float* __restrict__ bl,
                           const float* __restrict__ Wr, const float* __restrict__ br) {
    extern __shared__ float sm[];
    float* Wt4  = sm;                   // 160*160 floats (float4-packed)
    float* buf0 = sm + DIM * DIM;       // 96*160
    float* buf1 = buf0 + TILE * DIM;    // 96*160
    const float* W    = blockIdx.y ? Wr : Wl;
    const float* bias = blockIdx.y ? br : bl;
    float* out        = blockIdx.y ? g_xr : g_xl;
    int tid = threadIdx.x, lane = tid & 31, warp = tid >> 5;

    load_W_t4(Wt4, W, tid, 512);
    float bv[5];
    #pragma unroll
    for (int c = 0; c < 5; c++) bv[c] = bias[lane + 32 * c];

    int ntiles = (NN + TILE - 1) / TILE;
    float* cur = buf0; float* nxt = buf1;
    tile_load_async(cur, x, (long)blockIdx.x * TILE, NN, tid);
    asm volatile("cp.async.commit_group;\n");
    for (int t = blockIdx.x; t < ntiles; t += gridDim.x) {
        tile_load_async(nxt, x, (long)(t + gridDim.x) * TILE, NN, tid);
        asm volatile("cp.async.commit_group;\n");
        asm volatile("cp.async.wait_group 1;\n");
        __syncthreads();
        ull acc[RPW][5];
        gemm_tile_f2(Wt4, cur, warp, lane, acc);
        long r0 = (long)t * TILE + warp * RPW;
        #pragma unroll
        for (int r = 0; r < RPW; r++) {
            long gr = r0 + r;
            if (gr < NN) {
                #pragma unroll
                for (int c = 0; c < 5; c++)
                    out[gr * DIM + lane + 32 * c] = unpack_add(acc[r][c]) + bv[c];
            }
        }
        __syncthreads();
        float* tmp = cur; cur = nxt; nxt = tmp;
    }
}

// ---- K: ea = edge_attr@We — PURE GEMM, rows scattered into CSR order ------
__global__ __launch_bounds__(512, 1)
void edge_gemm_kernel(const float* __restrict__ edge_attr,
                      const float* __restrict__ We) {
    extern __shared__ float sm[];
    float* Wt4   = sm;
    float* buf0  = sm + DIM * DIM;
    float* buf1  = buf0 + TILE * DIM;
    int tid = threadIdx.x, lane = tid & 31, warp = tid >> 5;

    load_W_t4(Wt4, We, tid, 512);

    int ntiles = (NE + TILE - 1) / TILE;
    float* cur = buf0; float* nxt = buf1;
    tile_load_async(cur, edge_attr, (long)blockIdx.x * TILE, NE, tid);
    asm volatile("cp.async.commit_group;\n");
    for (int t = blockIdx.x; t < ntiles; t += gridDim.x) {
        tile_load_async(nxt, edge_attr, (long)(t + gridDim.x) * TILE, NE, tid);
        asm volatile("cp.async.commit_group;\n");
        asm volatile("cp.async.wait_group 1;\n");
        __syncthreads();
        ull acc[RPW][5];
        gemm_tile_f2(Wt4, cur, warp, lane, acc);
        int e0 = t * TILE + warp * RPW;
        #pragma unroll
        for (int r = 0; r < RPW; r++) {
            int e = e0 + r;
            if (e < NE) {                      // uniform across warp
                size_t pos = (size_t)g_pos[e];
                float* orow = g_ea + pos * DIM;
                #pragma unroll
                for (int c = 0; c < 5; c++)
                    orow[lane + 32 * c] = unpack_add(acc[r][c]);
            }
        }
        __syncthreads();
        float* tmp = cur; cur = nxt; nxt = tmp;
    }
}

// ---- fused score + softmax + aggregate (warp per node, CSR sequential) ----
__global__ __launch_bounds__(256)
void softagg_kernel(const float* __restrict__ att) {
    __shared__ float att_s[DIM];
    int tid = threadIdx.x;
    if (tid < DIM) att_s[tid] = att[tid];
    __syncthreads();
    int w = (int)(((long)blockIdx.x * blockDim.x + tid) >> 5);
    int lane = tid & 31;
    if (w >= NN) return;
    long off = g_off[w]; int deg = g_deg[w];
    const float* xrr = g_xr + (long)w * DIM + lane;
    float xr0 = xrr[0], xr1 = xrr[32], xr2 = xrr[64], xr3 = xrr[96], xr4 = xrr[128];
    float av0 = att_s[lane],      av1 = att_s[lane + 32], av2 = att_s[lane + 64],
          av3 = att_s[lane + 96], av4 = att_s[lane + 128];
    float a0 = 0.f, a1 = 0.f, a2 = 0.f, a3 = 0.f, a4 = 0.f;
    float s0 = 0.f, s1 = 0.f, s2 = 0.f, s3 = 0.f, s4 = 0.f;
    const int* sp = g_csrc + off;
    #pragma unroll 2
    for (int i = 0; i < deg; i++) {
        const float* ear = g_ea + (off + (long)i) * DIM + lane;  // sequential stream
        int s = sp[i];                                           // broadcast
        const float* xlr = g_xl + (long)s * DIM + lane;          // L2-hot gather
        float xl0 = xlr[0], xl1 = xlr[32], xl2 = xlr[64], xl3 = xlr[96], xl4 = xlr[128];
        float m0 = __ldcs(ear)       + xl0 + xr0;
        float m1 = __ldcs(ear + 32)  + xl1 + xr1;
        float m2 = __ldcs(ear + 64)  + xl2 + xr2;
        float m3 = __ldcs(ear + 96)  + xl3 + xr3;
        float m4 = __ldcs(ear + 128) + xl4 + xr4;
        m0 = (m0 > 0.f) ? m0 : 0.2f * m0;
        m1 = (m1 > 0.f) ? m1 : 0.2f * m1;
        m2 = (m2 > 0.f) ? m2 : 0.2f * m2;
        m3 = (m3 > 0.f) ? m3 : 0.2f * m3;
        m4 = (m4 > 0.f) ? m4 : 0.2f * m4;
        float p0 = m0 * av0, p1 = m1 * av1, p2 = m2 * av2, p3 = m3 * av3, p4 = m4 * av4;
        #pragma unroll
        for (int o = 16; o; o >>= 1) {
            p0 += __shfl_xor_sync(0xffffffffu, p0, o);
            p1 += __shfl_xor_sync(0xffffffffu, p1, o);
            p2 += __shfl_xor_sync(0xffffffffu, p2, o);
            p3 += __shfl_xor_sync(0xffffffffu, p3, o);
            p4 += __shfl_xor_sync(0xffffffffu, p4, o);
        }
        float w0 = __expf(p0), w1 = __expf(p1), w2 = __expf(p2);
        float w3 = __expf(p3), w4 = __expf(p4);
        s0 += w0; s1 += w1; s2 += w2; s3 += w3; s4 += w4;
        a0 = fmaf(w0, xl0, a0);
        a1 = fmaf(w1, xl1, a1);
        a2 = fmaf(w2, xl2, a2);
        a3 = fmaf(w3, xl3, a3);
        a4 = fmaf(w4, xl4, a4);
    }
    float* o = g_attn + (long)w * DIM + lane;
    if (deg > 0) {
        o[0]   = a0 / s0;
        o[32]  = a1 / s1;
        o[64]  = a2 / s2;
        o[96]  = a3 / s3;
        o[128] = a4 / s4;
    } else {
        o[0] = 0.f; o[32] = 0.f; o[64] = 0.f; o[96] = 0.f; o[128] = 0.f;
    }
}

// ------- fused tail: LN1 -> MLP(160->50->160) -> LN2, FFMA2 GEMMs ----------
__global__ __launch_bounds__(256, 2)
void tail_kernel(const float* __restrict__ x, const float* __restrict__ bias,
                 const float* __restrict__ g1, const float* __restrict__ bt1,
                 const float* __restrict__ W1, const float* __restrict__ b1,
                 const float* __restrict__ gm, const float* __restrict__ bm,
                 const float* __restrict__ W2, const float* __restrict__ b2,
                 const float* __restrict__ g2, const float* __restrict__ bt2,
                 float* __restrict__ out) {
    extern __shared__ float sm[];
    float* W1t   = sm;                  // 50 x W1S (transposed [c][k])
    float* W2t   = W1t + MH * W1S;      // 160 x W2S (transposed [c][k])
    float* hbuf  = W2t + DIM * W2S;     // 32 x HBS
    float* tbuf  = hbuf + 32 * HBS;     // 32 x TBS
    float* bias_s = tbuf + 32 * TBS;
    float* g1_s  = bias_s + DIM;
    float* bt1_s = g1_s + DIM;
    float* b2_s  = bt1_s + DIM;
    float* g2_s  = b2_s + DIM;
    float* bt2_s = g2_s + DIM;
    float* b1_s  = bt2_s + DIM;
    float* gm_s  = b1_s + MH;
    float* bm_s  = gm_s + MH;
    int tid = threadIdx.x, lane = tid & 31, warp = tid >> 5;

    for (int i = tid; i < DIM * MH; i += 256) {
        int kk = i / MH, cc = i - kk * MH;           // W1[k][c]
        W1t[cc * W1S + kk] = W1[i];
    }
    for (int i = tid; i < MH * DIM; i += 256) {
        int kk = i / DIM, cc = i - kk * DIM;         // W2[k][c]
        W2t[cc * W2S + kk] = W2[i];
    }
    if (tid < DIM) {
        bias_s[tid] = bias[tid]; g1_s[tid] = g1[tid]; bt1_s[tid] = bt1[tid];
        b2_s[tid] = b2[tid]; g2_s[tid] = g2[tid]; bt2_s[tid] = bt2[tid];
    }
    if (tid < MH) { b1_s[tid] = b1[tid]; gm_s[tid] = gm[tid]; bm_s[tid] = bm[tid]; }
    __syncthreads();

    for (int chunk = blockIdx.x; chunk < NCHUNK; chunk += gridDim.x) {
        int n0 = chunk * 32;
        // --- phase A: h = LN(x + attn + bias) -> hbuf (warp per node) ---
        #pragma unroll
        for (int i = 0; i < 4; i++) {
            int nl = warp + 8 * i;
            long n = n0 + nl;
            float v[5];
            if (n < NN) {
                #pragma unroll
                for (int c = 0; c < 5; c++) {
                    int col = lane + 32 * c;
                    v[c] = x[n * DIM + col] + g_attn[n * DIM + col] + bias_s[col];
                }
            } else {
                #pragma unroll
                for (int c = 0; c < 5; c++) v[c] = 0.f;
            }
            float p1 = 0.f, p2 = 0.f;
            #pragma unroll
            for (int c = 0; c < 5; c++) { p1 += v[c]; p2 += v[c] * v[c]; }
            #pragma unroll
            for (int off = 16; off; off >>= 1) {
                p1 += __shfl_xor_sync(0xffffffffu, p1, off);
                p2 += __shfl_xor_sync(0xffffffffu, p2, off);
            }
            float mu = p1 * (1.f / DIM);
            float rstd = rsqrtf(p2 * (1.f / DIM) - mu * mu + 1e-5f);
            #pragma unroll
            for (int c = 0; c < 5; c++) {
                int col = lane + 32 * c;
                hbuf[nl * HBS + col] = (v[c] - mu) * rstd * g1_s[col] + bt1_s[col];
            }
        }
        __syncthreads();
        // --- phase B: t = selu(h@W1 + b1) -> tbuf (FFMA2 over k-pairs) ---
        {
            int cg = lane, ng = warp;
            ull a0[4] = {0ull,0ull,0ull,0ull}, a1[4] = {0ull,0ull,0ull,0ull};
            #pragma unroll 4
            for (int k = 0; k < DIM; k += 2) {
                ull w0 = *(const ull*)(W1t + cg * W1S + k);
                ull w1 = (cg < MH - 32) ? *(const ull*)(W1t + (cg + 32) * W1S + k) : 0ull;
                #pragma unroll
                for (int i = 0; i < 4; i++) {
                    ull hv = *(const ull*)(hbuf + (ng * 4 + i) * HBS + k);
                    FFMA2(a0[i], hv, w0);
                    FFMA2(a1[i], hv, w1);
                }
            }
            #pragma unroll
            for (int i = 0; i < 4; i++) {
                int nl = ng * 4 + i;
                tbuf[nl * TBS + cg] = selu_f(unpack_add(a0[i]) + b1_s[cg]);
                if (cg < MH - 32)
                    tbuf[nl * TBS + cg + 32] = selu_f(unpack_add(a1[i]) + b1_s[cg + 32]);
            }
        }
        __syncthreads();
        // --- LN over 50 (thread per node) ---
        if (tid < 32) {
            float p1 = 0.f, p2 = 0.f;
            for (int k = 0; k < MH; k++) { float t = tbuf[tid * TBS + k]; p1 += t; p2 += t * t; }
            float mu = p1 * (1.f / MH);
            float rstd = rsqrtf(p2 * (1.f / MH) - mu * mu + 1e-5f);
            for (int k = 0; k < MH; k++)
                tbuf[tid * TBS + k] = (tbuf[tid * TBS + k] - mu) * rstd * gm_s[k] + bm_s[k];
        }
        __syncthreads();
        // --- phase C: mlp = u@W2 + b2; out = LN(h + mlp) (FFMA2 over k) ---
        {
            ull acc[4][5];
            #pragma unroll
            for (int i = 0; i < 4; i++)
                #pragma unroll
                for (int c = 0; c < 5; c++) acc[i][c] = 0ull;
            #pragma unroll 5
            for (int k = 0; k < MH; k += 2) {
                ull wv[5];
                #pragma unroll
                for (int c = 0; c < 5; c++)
                    wv[c] = *(const ull*)(W2t + (lane + 32 * c) * W2S + k);
                #pragma unroll
                for (int i = 0; i < 4; i++) {
                    ull uv = *(const ull*)(tbuf + (warp * 4 + i) * TBS + k);
                    #pragma unroll
                    for (int c = 0; c < 5; c++) FFMA2(acc[i][c], uv, wv[c]);
                }
            }
            #pragma unroll
            for (int i = 0; i < 4; i++) {
                int nl = warp * 4 + i;
                long n = n0 + nl;
                float v[5];
                #pragma unroll
                for (int c = 0; c < 5; c++) {
                    int col = lane + 32 * c;
                    v[c] = hbuf[nl * HBS + col] + unpack_add(acc[i][c]) + b2_s[col];
                }
                float p1 = 0.f, p2 = 0.f;
                #pragma unroll
                for (int c = 0; c < 5; c++) { p1 += v[c]; p2 += v[c] * v[c]; }
                #pragma unroll
                for (int off = 16; off; off >>= 1) {
                    p1 += __shfl_xor_sync(0xffffffffu, p1, off);
                    p2 += __shfl_xor_sync(0xffffffffu, p2, off);
                }
                float mu = p1 * (1.f / DIM);
                float rstd = rsqrtf(p2 * (1.f / DIM) - mu * mu + 1e-5f);
                if (n < NN) {
                    #pragma unroll
                    for (int c = 0; c < 5; c++) {
                        int col = lane + 32 * c;
                        out[n * DIM + col] = (v[c] - mu) * rstd * g2_s[col] + bt2_s[col];
                    }
                }
            }
        }
        __syncthreads();
    }
}

// ---------------- launch ----------------
extern "C" void kernel_launch(void* const* d_in, const int* in_sizes, int n_in,
                              void* d_out, int out_size) {
    const float* x         = (const float*)d_in[0];
    const int*   edge_index= (const int*)d_in[1];
    const float* edge_attr = (const float*)d_in[2];
    const float* Wl  = (const float*)d_in[5];
    const float* bl  = (const float*)d_in[6];
    const float* Wr  = (const float*)d_in[7];
    const float* br  = (const float*)d_in[8];
    const float* We  = (const float*)d_in[9];
    const float* att = (const float*)d_in[10];
    const float* bias= (const float*)d_in[11];
    const float* g1  = (const float*)d_in[12];
    const float* bt1 = (const float*)d_in[13];
    const float* W1  = (const float*)d_in[14];
    const float* b1  = (const float*)d_in[15];
    const float* gm  = (const float*)d_in[16];
    const float* bm  = (const float*)d_in[17];
    const float* W2  = (const float*)d_in[18];
    const float* b2  = (const float*)d_in[19];
    const float* g2  = (const float*)d_in[20];
    const float* bt2 = (const float*)d_in[21];
    float* out = (float*)d_out;
    const int* src = edge_index;
    const int* dst = edge_index + NE;

    const int SM_GEMM = (DIM * DIM + 2 * TILE * DIM) * (int)sizeof(float);       // 225280
    const int SM_TAIL = (MH * W1S + DIM * W2S + 32 * HBS + 32 * TBS + 6 * DIM + 3 * MH)
                        * (int)sizeof(float);
    cudaFuncSetAttribute(node_transform_kernel, cudaFuncAttributeMaxDynamicSharedMemorySize, SM_GEMM);
    cudaFuncSetAttribute(edge_gemm_kernel,      cudaFuncAttributeMaxDynamicSharedMemorySize, SM_GEMM);
    cudaFuncSetAttribute(tail_kernel,           cudaFuncAttributeMaxDynamicSharedMemorySize, SM_TAIL);

    node_transform_kernel<<<dim3(148, 2), 512, SM_GEMM>>>(x, Wl, bl, Wr, br);  // 0
    zero_deg_kernel<<<(NN + 255) / 256, 256>>>();                              // 1
    count_kernel<<<(NE + 255) / 256, 256>>>(dst);                              // 2
    scan1_kernel<<<NB, 256>>>();                                               // 3
    scan2_kernel<<<1, 256>>>();                                                // 4
    scan3_kernel<<<(NN + 255) / 256, 256>>>();                                 // 5
    fill_kernel<<<(NE + 255) / 256, 256>>>(src, dst);                          // 6
    edge_gemm_kernel<<<148, 512, SM_GEMM>>>(edge_attr, We);                    // 7
    softagg_kernel<<<(NN + 7) / 8, 256>>>(att);                                // 8
    tail_kernel<<<296, 256, SM_TAIL>>>(x, bias, g1, bt1, W1, b1, gm, bm,
                                       W2, b2, g2, bt2, out);                  // 9
}

// round 15
// speedup vs baseline: 2.1586x; 1.4292x over previous
#include <cuda_runtime.h>
#include <cuda_bf16.h>
#include <cstdint>

typedef unsigned long long ull;

#define NN    50000
#define NE    500000
#define DIM   160
#define HEADS 5
#define MH    50
#define NV4   (DIM/4)
#define TILE  96
#define RPW   6
#define NB    ((NN + 255) / 256)
#define NCHUNK ((NN + 31) / 32)
#define HBS   162
#define TBS   52
#define W1S   162
#define W2S   54

// ---- HMMA edge GEMM constants ----
#define MT      128
#define NTILES  ((NE + MT - 1) / MT)     // 3907
#define EAST    168                      // bf16 row stride (336B: conflict-free ldmatrix)
#define SMA_HI  0
#define SMA_LO  43008                    // 128*168*2
#define SMB_HI  86016
#define SMB_LO  139776                   // + 160*168*2
#define SM_EDGE_TC 193536

// ---------------- scratch ----------------
__device__ float g_xl[NN * DIM];
__device__ float g_xr[NN * DIM];
__device__ float g_attn[NN * DIM];
__device__ float g_ea[(size_t)NE * DIM];   // edge GEMM out, edge order (320 MB)
__device__ int   g_csrc[NE];
__device__ int   g_eid[NE];
__device__ int   g_deg[NN];
__device__ int   g_off[NN];
__device__ int   g_cur[NN];
__device__ int   g_bsum[256];

__device__ __forceinline__ float selu_f(float v) {
    const float sc = 1.0507009873554805f, al = 1.6732632423543772f;
    return v > 0.f ? sc * v : sc * al * (expf(v) - 1.f);
}

#define FFMA2(d, a, b) asm("fma.rn.f32x2 %0, %1, %2, %0;" : "+l"(d) : "l"(a), "l"(b))

__device__ __forceinline__ float unpack_add(ull v) {
    return __uint_as_float((unsigned)v) + __uint_as_float((unsigned)(v >> 32));
}

// ---------------- CSR build ----------------
__global__ void zero_deg_kernel() {
    int i = blockIdx.x * blockDim.x + threadIdx.x;
    if (i < NN) g_deg[i] = 0;
}
__global__ void count_kernel(const int* __restrict__ dst) {
    int e = blockIdx.x * blockDim.x + threadIdx.x;
    if (e < NE) atomicAdd(&g_deg[dst[e]], 1);
}
__global__ void scan1_kernel() {
    __shared__ int wsum[8];
    int tid = threadIdx.x, lane = tid & 31, warp = tid >> 5;
    int i = blockIdx.x * 256 + tid;
    int v = (i < NN) ? g_deg[i] : 0;
    int x = v;
    #pragma unroll
    for (int d = 1; d < 32; d <<= 1) {
        int y = __shfl_up_sync(0xffffffffu, x, d);
        if (lane >= d) x += y;
    }
    if (lane == 31) wsum[warp] = x;
    __syncthreads();
    if (tid == 0) {
        int s = 0;
        #pragma unroll
        for (int j = 0; j < 8; j++) { int t = wsum[j]; wsum[j] = s; s += t; }
        g_bsum[blockIdx.x] = s;
    }
    __syncthreads();
    if (i < NN) g_off[i] = x - v + wsum[warp];
}
__global__ void scan2_kernel() {
    __shared__ int wsum[8];
    int tid = threadIdx.x, lane = tid & 31, warp = tid >> 5;
    int v = (tid < NB) ? g_bsum[tid] : 0;
    int x = v;
    #pragma unroll
    for (int d = 1; d < 32; d <<= 1) {
        int y = __shfl_up_sync(0xffffffffu, x, d);
        if (lane >= d) x += y;
    }
    if (lane == 31) wsum[warp] = x;
    __syncthreads();
    if (tid == 0) {
        int s = 0;
        #pragma unroll
        for (int j = 0; j < 8; j++) { int t = wsum[j]; wsum[j] = s; s += t; }
    }
    __syncthreads();
    if (tid < NB) g_bsum[tid] = x - v + wsum[warp];
}
__global__ void scan3_kernel() {
    int i = blockIdx.x * blockDim.x + threadIdx.x;
    if (i < NN) {
        int o = g_off[i] + g_bsum[i >> 8];
        g_off[i] = o;
        g_cur[i] = o;
    }
}
__global__ void fill_kernel(const int* __restrict__ src, const int* __restrict__ dst) {
    int e = blockIdx.x * blockDim.x + threadIdx.x;
    if (e < NE) {
        int pos = atomicAdd(&g_cur[dst[e]], 1);
        g_eid[pos] = e;
        g_csrc[pos] = src[e];
    }
}

// ---------------- cp.async tile loader ----------------
__device__ __forceinline__ void tile_load_async(float* buf, const float* src_mat,
                                                long row0, long nrows, int tid) {
    unsigned base = (unsigned)__cvta_generic_to_shared(buf);
    #pragma unroll
    for (int it = 0; it < 8; it++) {
        int i = tid + it * 512;
        if (i < TILE * NV4) {
            int r = i / NV4;
            long row = row0 + r;
            const float4* p = (const float4*)src_mat +
                              (row < nrows ? row * NV4 + (i - r * NV4) : 0);
            int sz = (row < nrows) ? 16 : 0;
            asm volatile("cp.async.cg.shared.global [%0], [%1], 16, %2;\n"
                         :: "r"(base + (unsigned)i * 16u), "l"(p), "r"(sz));
        }
    }
}

// ---- f32x2 SIMT GEMM mainloop (node transform) ----
__device__ __forceinline__ void gemm_tile_f2(const float* __restrict__ Wt4,
                                             const float* __restrict__ a_s,
                                             int warp, int lane, ull acc[RPW][5]) {
    #pragma unroll
    for (int r = 0; r < RPW; r++)
        #pragma unroll
        for (int c = 0; c < 5; c++) acc[r][c] = 0ull;
    const float* arow = a_s + warp * RPW * DIM;
    const ulonglong2* wq = (const ulonglong2*)Wt4;
    #pragma unroll 2
    for (int k = 0; k < DIM; k += 4) {
        ulonglong2 xv[RPW];
        #pragma unroll
        for (int r = 0; r < RPW; r++)
            xv[r] = *(const ulonglong2*)(arow + r * DIM + k);
        ulonglong2 wv[5];
        int base = (k >> 2) * DIM + lane;
        #pragma unroll
        for (int c = 0; c < 5; c++)
            wv[c] = wq[base + 32 * c];
        #pragma unroll
        for (int r = 0; r < RPW; r++)
            #pragma unroll
            for (int c = 0; c < 5; c++) {
                FFMA2(acc[r][c], xv[r].x, wv[c].x);
                FFMA2(acc[r][c], xv[r].y, wv[c].y);
            }
    }
}

__device__ __forceinline__ void load_W_t4(float* Wt4, const float* W, int tid, int nthr) {
    for (int i = tid; i < DIM * DIM; i += nthr) {
        int kk = i / DIM, cc = i - kk * DIM;
        Wt4[(((kk >> 2) * DIM) + cc) * 4 + (kk & 3)] = W[i];
    }
}

// ---------------- K: xl = x@Wl+bl, xr = x@Wr+br ------------
__global__ __launch_bounds__(512, 1)
void node_transform_kernel(const float* __restrict__ x,
                           const float* __restrict__ Wl, const float* __restrict__ bl,
                           const float* __restrict__ Wr, const float* __restrict__ br) {
    extern __shared__ float sm[];
    float* Wt4  = sm;
    float* buf0 = sm + DIM * DIM;
    float* buf1 = buf0 + TILE * DIM;
    const float* W    = blockIdx.y ? Wr : Wl;
    const float* bias = blockIdx.y ? br : bl;
    float* out        = blockIdx.y ? g_xr : g_xl;
    int tid = threadIdx.x, lane = tid & 31, warp = tid >> 5;

    load_W_t4(Wt4, W, tid, 512);
    float bv[5];
    #pragma unroll
    for (int c = 0; c < 5; c++) bv[c] = bias[lane + 32 * c];

    int ntiles = (NN + TILE - 1) / TILE;
    float* cur = buf0; float* nxt = buf1;
    tile_load_async(cur, x, (long)blockIdx.x * TILE, NN, tid);
    asm volatile("cp.async.commit_group;\n");
    for (int t = blockIdx.x; t < ntiles; t += gridDim.x) {
        tile_load_async(nxt, x, (long)(t + gridDim.x) * TILE, NN, tid);
        asm volatile("cp.async.commit_group;\n");
        asm volatile("cp.async.wait_group 1;\n");
        __syncthreads();
        ull acc[RPW][5];
        gemm_tile_f2(Wt4, cur, warp, lane, acc);
        long r0 = (long)t * TILE + warp * RPW;
        #pragma unroll
        for (int r = 0; r < RPW; r++) {
            long gr = r0 + r;
            if (gr < NN) {
                #pragma unroll
                for (int c = 0; c < 5; c++)
                    out[gr * DIM + lane + 32 * c] = unpack_add(acc[r][c]) + bv[c];
            }
        }
        __syncthreads();
        float* tmp = cur; cur = nxt; nxt = tmp;
    }
}

// ================= HMMA (mma.sync) bf16x3-split edge GEMM =================
#define MMA16816(c, a, b0, b1) \
    asm volatile("mma.sync.aligned.m16n8k16.row.col.f32.bf16.bf16.f32 " \
        "{%0,%1,%2,%3}, {%4,%5,%6,%7}, {%8,%9}, {%0,%1,%2,%3};" \
        : "+f"((c)[0]), "+f"((c)[1]), "+f"((c)[2]), "+f"((c)[3]) \
        : "r"((a)[0]), "r"((a)[1]), "r"((a)[2]), "r"((a)[3]), "r"(b0), "r"(b1))

#define LDMX4(r, addr) \
    asm volatile("ldmatrix.sync.aligned.m8n8.x4.shared.b16 {%0,%1,%2,%3}, [%4];" \
        : "=r"((r)[0]), "=r"((r)[1]), "=r"((r)[2]), "=r"((r)[3]) : "r"(addr))

__global__ __launch_bounds__(512, 1)
void edge_gemm_tc(const float* __restrict__ edge_attr, const float* __restrict__ We) {
    extern __shared__ char smc[];
    unsigned sbase = (unsigned)__cvta_generic_to_shared(smc);
    int tid = threadIdx.x, lane = tid & 31, wid = tid >> 5;
    int wm = wid & 7;            // m-group: rows wm*16 .. wm*16+15
    int wn = wid >> 3;           // n-half: cols wn*80 .. wn*80+79

    // B = We^T split: Bt[n][k] = We[k*DIM + n]
    for (int i = tid; i < DIM * DIM; i += 512) {
        int k = i / DIM, n = i - k * DIM;
        float v = We[i];
        __nv_bfloat16 h = __float2bfloat16(v);
        __nv_bfloat16 l = __float2bfloat16(v - __bfloat162float(h));
        unsigned off = (unsigned)(n * EAST + k) * 2u;
        *(unsigned short*)(smc + SMB_HI + off) = __bfloat16_as_ushort(h);
        *(unsigned short*)(smc + SMB_LO + off) = __bfloat16_as_ushort(l);
    }

    // ldmatrix per-lane address components
    int arow = lane & 15, akb = (lane >> 4) << 3;                 // A: 4 mats m0k0/m8k0/m0k8/m8k8
    int brow = (lane & 7) + ((lane >> 4) << 3), bkb = lane & 8;   // B: n0k0/n0k8/n8k0/n8k8
    unsigned abase = sbase + (unsigned)((wm * 16 + arow) * EAST + akb) * 2u;
    unsigned bbase = sbase + (unsigned)(brow * EAST + bkb) * 2u;

    for (long t = blockIdx.x; t < NTILES; t += gridDim.x) {
        long eb = t * MT;
        // A tile: fp32 -> hi/lo bf16 (rows=edges, cols=k)
        #pragma unroll
        for (int it = 0; it < 10; it++) {
            int j = tid + it * 512;                  // 128*40 float4 slots
            int row = j / 40, c4 = j - row * 40, col = c4 * 4;
            long rg = eb + row;
            if (rg >= NE) rg = 0;
            float4 v = *(const float4*)(edge_attr + rg * DIM + col);
            __nv_bfloat16 h0 = __float2bfloat16(v.x), h1 = __float2bfloat16(v.y);
            __nv_bfloat16 h2 = __float2bfloat16(v.z), h3 = __float2bfloat16(v.w);
            __nv_bfloat16 l0 = __float2bfloat16(v.x - __bfloat162float(h0));
            __nv_bfloat16 l1 = __float2bfloat16(v.y - __bfloat162float(h1));
            __nv_bfloat16 l2 = __float2bfloat16(v.z - __bfloat162float(h2));
            __nv_bfloat16 l3 = __float2bfloat16(v.w - __bfloat162float(h3));
            ull hp = (ull)__bfloat16_as_ushort(h0) | ((ull)__bfloat16_as_ushort(h1) << 16)
                   | ((ull)__bfloat16_as_ushort(h2) << 32) | ((ull)__bfloat16_as_ushort(h3) << 48);
            ull lp = (ull)__bfloat16_as_ushort(l0) | ((ull)__bfloat16_as_ushort(l1) << 16)
                   | ((ull)__bfloat16_as_ushort(l2) << 32) | ((ull)__bfloat16_as_ushort(l3) << 48);
            unsigned off = (unsigned)(row * EAST + col) * 2u;
            *(ull*)(smc + SMA_HI + off) = hp;
            *(ull*)(smc + SMA_LO + off) = lp;
        }
        __syncthreads();

        float c[10][4];
        #pragma unroll
        for (int j = 0; j < 10; j++)
            #pragma unroll
            for (int q = 0; q < 4; q++) c[j][q] = 0.f;

        #pragma unroll
        for (int kc = 0; kc < 10; kc++) {
            unsigned k2 = (unsigned)(kc * 16) * 2u;
            unsigned ah[4], al[4];
            LDMX4(ah, abase + SMA_HI + k2);
            LDMX4(al, abase + SMA_LO + k2);
            #pragma unroll
            for (int jp = 0; jp < 5; jp++) {
                unsigned noff = (unsigned)((wn * 80 + jp * 16) * EAST) * 2u;
                unsigned bh[4], bl[4];
                LDMX4(bh, bbase + SMB_HI + noff + k2);
                LDMX4(bl, bbase + SMB_LO + noff + k2);
                int j0 = jp * 2, j1 = j0 + 1;
                MMA16816(c[j0], ah, bh[0], bh[1]);
                MMA16816(c[j1], ah, bh[2], bh[3]);
                MMA16816(c[j0], al, bh[0], bh[1]);
                MMA16816(c[j1], al, bh[2], bh[3]);
                MMA16816(c[j0], ah, bl[0], bl[1]);
                MMA16816(c[j1], ah, bl[2], bl[3]);
            }
        }

        // epilogue: coalesced edge-order stores
        long e1 = eb + wm * 16 + (lane >> 2);
        long e2 = e1 + 8;
        int ncol = wn * 80 + 2 * (lane & 3);
        #pragma unroll
        for (int j = 0; j < 10; j++) {
            int n = ncol + j * 8;
            if (e1 < NE) *(float2*)(g_ea + (size_t)e1 * DIM + n) = make_float2(c[j][0], c[j][1]);
            if (e2 < NE) *(float2*)(g_ea + (size_t)e2 * DIM + n) = make_float2(c[j][2], c[j][3]);
        }
        __syncthreads();
    }
}

// ---- fused score + softmax + aggregate (warp per node; ea via eid gather) --
__global__ __launch_bounds__(256)
void softagg_kernel(const float* __restrict__ att) {
    __shared__ float att_s[DIM];
    int tid = threadIdx.x;
    if (tid < DIM) att_s[tid] = att[tid];
    __syncthreads();
    int w = (int)(((long)blockIdx.x * blockDim.x + tid) >> 5);
    int lane = tid & 31;
    if (w >= NN) return;
    long off = g_off[w]; int deg = g_deg[w];
    const float* xrr = g_xr + (long)w * DIM + lane;
    float xr0 = xrr[0], xr1 = xrr[32], xr2 = xrr[64], xr3 = xrr[96], xr4 = xrr[128];
    float av0 = att_s[lane],      av1 = att_s[lane + 32], av2 = att_s[lane + 64],
          av3 = att_s[lane + 96], av4 = att_s[lane + 128];
    float a0 = 0.f, a1 = 0.f, a2 = 0.f, a3 = 0.f, a4 = 0.f;
    float s0 = 0.f, s1 = 0.f, s2 = 0.f, s3 = 0.f, s4 = 0.f;
    const int* sp = g_csrc + off;
    const int* ep = g_eid + off;
    #pragma unroll 2
    for (int i = 0; i < deg; i++) {
        long e = ep[i];                                          // broadcast
        const float* ear = g_ea + (size_t)e * DIM + lane;
        int s = sp[i];                                           // broadcast
        const float* xlr = g_xl + (long)s * DIM + lane;
        float xl0 = xlr[0], xl1 = xlr[32], xl2 = xlr[64], xl3 = xlr[96], xl4 = xlr[128];
        float m0 = __ldcs(ear)       + xl0 + xr0;
        float m1 = __ldcs(ear + 32)  + xl1 + xr1;
        float m2 = __ldcs(ear + 64)  + xl2 + xr2;
        float m3 = __ldcs(ear + 96)  + xl3 + xr3;
        float m4 = __ldcs(ear + 128) + xl4 + xr4;
        m0 = (m0 > 0.f) ? m0 : 0.2f * m0;
        m1 = (m1 > 0.f) ? m1 : 0.2f * m1;
        m2 = (m2 > 0.f) ? m2 : 0.2f * m2;
        m3 = (m3 > 0.f) ? m3 : 0.2f * m3;
        m4 = (m4 > 0.f) ? m4 : 0.2f * m4;
        float p0 = m0 * av0, p1 = m1 * av1, p2 = m2 * av2, p3 = m3 * av3, p4 = m4 * av4;
        #pragma unroll
        for (int o = 16; o; o >>= 1) {
            p0 += __shfl_xor_sync(0xffffffffu, p0, o);
            p1 += __shfl_xor_sync(0xffffffffu, p1, o);
            p2 += __shfl_xor_sync(0xffffffffu, p2, o);
            p3 += __shfl_xor_sync(0xffffffffu, p3, o);
            p4 += __shfl_xor_sync(0xffffffffu, p4, o);
        }
        float w0 = __expf(p0), w1 = __expf(p1), w2 = __expf(p2);
        float w3 = __expf(p3), w4 = __expf(p4);
        s0 += w0; s1 += w1; s2 += w2; s3 += w3; s4 += w4;
        a0 = fmaf(w0, xl0, a0);
        a1 = fmaf(w1, xl1, a1);
        a2 = fmaf(w2, xl2, a2);
        a3 = fmaf(w3, xl3, a3);
        a4 = fmaf(w4, xl4, a4);
    }
    float* o = g_attn + (long)w * DIM + lane;
    if (deg > 0) {
        o[0]   = a0 / s0;
        o[32]  = a1 / s1;
        o[64]  = a2 / s2;
        o[96]  = a3 / s3;
        o[128] = a4 / s4;
    } else {
        o[0] = 0.f; o[32] = 0.f; o[64] = 0.f; o[96] = 0.f; o[128] = 0.f;
    }
}

// ------- fused tail: LN1 -> MLP(160->50->160) -> LN2, FFMA2 GEMMs ----------
__global__ __launch_bounds__(256, 2)
void tail_kernel(const float* __restrict__ x, const float* __restrict__ bias,
                 const float* __restrict__ g1, const float* __restrict__ bt1,
                 const float* __restrict__ W1, const float* __restrict__ b1,
                 const float* __restrict__ gm, const float* __restrict__ bm,
                 const float* __restrict__ W2, const float* __restrict__ b2,
                 const float* __restrict__ g2, const float* __restrict__ bt2,
                 float* __restrict__ out) {
    extern __shared__ float sm[];
    float* W1t   = sm;
    float* W2t   = W1t + MH * W1S;
    float* hbuf  = W2t + DIM * W2S;
    float* tbuf  = hbuf + 32 * HBS;
    float* bias_s = tbuf + 32 * TBS;
    float* g1_s  = bias_s + DIM;
    float* bt1_s = g1_s + DIM;
    float* b2_s  = bt1_s + DIM;
    float* g2_s  = b2_s + DIM;
    float* bt2_s = g2_s + DIM;
    float* b1_s  = bt2_s + DIM;
    float* gm_s  = b1_s + MH;
    float* bm_s  = gm_s + MH;
    int tid = threadIdx.x, lane = tid & 31, warp = tid >> 5;

    for (int i = tid; i < DIM * MH; i += 256) {
        int kk = i / MH, cc = i - kk * MH;
        W1t[cc * W1S + kk] = W1[i];
    }
    for (int i = tid; i < MH * DIM; i += 256) {
        int kk = i / DIM, cc = i - kk * DIM;
        W2t[cc * W2S + kk] = W2[i];
    }
    if (tid < DIM) {
        bias_s[tid] = bias[tid]; g1_s[tid] = g1[tid]; bt1_s[tid] = bt1[tid];
        b2_s[tid] = b2[tid]; g2_s[tid] = g2[tid]; bt2_s[tid] = bt2[tid];
    }
    if (tid < MH) { b1_s[tid] = b1[tid]; gm_s[tid] = gm[tid]; bm_s[tid] = bm[tid]; }
    __syncthreads();

    for (int chunk = blockIdx.x; chunk < NCHUNK; chunk += gridDim.x) {
        int n0 = chunk * 32;
        #pragma unroll
        for (int i = 0; i < 4; i++) {
            int nl = warp + 8 * i;
            long n = n0 + nl;
            float v[5];
            if (n < NN) {
                #pragma unroll
                for (int c = 0; c < 5; c++) {
                    int col = lane + 32 * c;
                    v[c] = x[n * DIM + col] + g_attn[n * DIM + col] + bias_s[col];
                }
            } else {
                #pragma unroll
                for (int c = 0; c < 5; c++) v[c] = 0.f;
            }
            float p1 = 0.f, p2 = 0.f;
            #pragma unroll
            for (int c = 0; c < 5; c++) { p1 += v[c]; p2 += v[c] * v[c]; }
            #pragma unroll
            for (int off = 16; off; off >>= 1) {
                p1 += __shfl_xor_sync(0xffffffffu, p1, off);
                p2 += __shfl_xor_sync(0xffffffffu, p2, off);
            }
            float mu = p1 * (1.f / DIM);
            float rstd = rsqrtf(p2 * (1.f / DIM) - mu * mu + 1e-5f);
            #pragma unroll
            for (int c = 0; c < 5; c++) {
                int col = lane + 32 * c;
                hbuf[nl * HBS + col] = (v[c] - mu) * rstd * g1_s[col] + bt1_s[col];
            }
        }
        __syncthreads();
        {
            int cg = lane, ng = warp;
            ull a0[4] = {0ull,0ull,0ull,0ull}, a1[4] = {0ull,0ull,0ull,0ull};
            #pragma unroll 4
            for (int k = 0; k < DIM; k += 2) {
                ull w0 = *(const ull*)(W1t + cg * W1S + k);
                ull w1 = (cg < MH - 32) ? *(const ull*)(W1t + (cg + 32) * W1S + k) : 0ull;
                #pragma unroll
                for (int i = 0; i < 4; i++) {
                    ull hv = *(const ull*)(hbuf + (ng * 4 + i) * HBS + k);
                    FFMA2(a0[i], hv, w0);
                    FFMA2(a1[i], hv, w1);
                }
            }
            #pragma unroll
            for (int i = 0; i < 4; i++) {
                int nl = ng * 4 + i;
                tbuf[nl * TBS + cg] = selu_f(unpack_add(a0[i]) + b1_s[cg]);
                if (cg < MH - 32)
                    tbuf[nl * TBS + cg + 32] = selu_f(unpack_add(a1[i]) + b1_s[cg + 32]);
            }
        }
        __syncthreads();
        if (tid < 32) {
            float p1 = 0.f, p2 = 0.f;
            for (int k = 0; k < MH; k++) { float t = tbuf[tid * TBS + k]; p1 += t; p2 += t * t; }
            float mu = p1 * (1.f / MH);
            float rstd = rsqrtf(p2 * (1.f / MH) - mu * mu + 1e-5f);
            for (int k = 0; k < MH; k++)
                tbuf[tid * TBS + k] = (tbuf[tid * TBS + k] - mu) * rstd * gm_s[k] + bm_s[k];
        }
        __syncthreads();
        {
            ull acc[4][5];
            #pragma unroll
            for (int i = 0; i < 4; i++)
                #pragma unroll
                for (int c = 0; c < 5; c++) acc[i][c] = 0ull;
            #pragma unroll 5
            for (int k = 0; k < MH; k += 2) {
                ull wv[5];
                #pragma unroll
                for (int c = 0; c < 5; c++)
                    wv[c] = *(const ull*)(W2t + (lane + 32 * c) * W2S + k);
                #pragma unroll
                for (int i = 0; i < 4; i++) {
                    ull uv = *(const ull*)(tbuf + (warp * 4 + i) * TBS + k);
                    #pragma unroll
                    for (int c = 0; c < 5; c++) FFMA2(acc[i][c], uv, wv[c]);
                }
            }
            #pragma unroll
            for (int i = 0; i < 4; i++) {
                int nl = warp * 4 + i;
                long n = n0 + nl;
                float v[5];
                #pragma unroll
                for (int c = 0; c < 5; c++) {
                    int col = lane + 32 * c;
                    v[c] = hbuf[nl * HBS + col] + unpack_add(acc[i][c]) + b2_s[col];
                }
                float p1 = 0.f, p2 = 0.f;
                #pragma unroll
                for (int c = 0; c < 5; c++) { p1 += v[c]; p2 += v[c] * v[c]; }
                #pragma unroll
                for (int off = 16; off; off >>= 1) {
                    p1 += __shfl_xor_sync(0xffffffffu, p1, off);
                    p2 += __shfl_xor_sync(0xffffffffu, p2, off);
                }
                float mu = p1 * (1.f / DIM);
                float rstd = rsqrtf(p2 * (1.f / DIM) - mu * mu + 1e-5f);
                if (n < NN) {
                    #pragma unroll
                    for (int c = 0; c < 5; c++) {
                        int col = lane + 32 * c;
                        out[n * DIM + col] = (v[c] - mu) * rstd * g2_s[col] + bt2_s[col];
                    }
                }
            }
        }
        __syncthreads();
    }
}

// ---------------- launch ----------------
extern "C" void kernel_launch(void* const* d_in, const int* in_sizes, int n_in,
                              void* d_out, int out_size) {
    const float* x         = (const float*)d_in[0];
    const int*   edge_index= (const int*)d_in[1];
    const float* edge_attr = (const float*)d_in[2];
    const float* Wl  = (const float*)d_in[5];
    const float* bl  = (const float*)d_in[6];
    const float* Wr  = (const float*)d_in[7];
    const float* br  = (const float*)d_in[8];
    const float* We  = (const float*)d_in[9];
    const float* att = (const float*)d_in[10];
    const float* bias= (const float*)d_in[11];
    const float* g1  = (const float*)d_in[12];
    const float* bt1 = (const float*)d_in[13];
    const float* W1  = (const float*)d_in[14];
    const float* b1  = (const float*)d_in[15];
    const float* gm  = (const float*)d_in[16];
    const float* bm  = (const float*)d_in[17];
    const float* W2  = (const float*)d_in[18];
    const float* b2  = (const float*)d_in[19];
    const float* g2  = (const float*)d_in[20];
    const float* bt2 = (const float*)d_in[21];
    float* out = (float*)d_out;
    const int* src = edge_index;
    const int* dst = edge_index + NE;

    const int SM_GEMM = (DIM * DIM + 2 * TILE * DIM) * (int)sizeof(float);
    const int SM_TAIL = (MH * W1S + DIM * W2S + 32 * HBS + 32 * TBS + 6 * DIM + 3 * MH)
                        * (int)sizeof(float);
    cudaFuncSetAttribute(node_transform_kernel, cudaFuncAttributeMaxDynamicSharedMemorySize, SM_GEMM);
    cudaFuncSetAttribute(edge_gemm_tc,          cudaFuncAttributeMaxDynamicSharedMemorySize, SM_EDGE_TC);
    cudaFuncSetAttribute(tail_kernel,           cudaFuncAttributeMaxDynamicSharedMemorySize, SM_TAIL);

    node_transform_kernel<<<dim3(148, 2), 512, SM_GEMM>>>(x, Wl, bl, Wr, br);  // 0
    zero_deg_kernel<<<(NN + 255) / 256, 256>>>();                              // 1
    count_kernel<<<(NE + 255) / 256, 256>>>(dst);                              // 2
    edge_gemm_tc<<<148, 512, SM_EDGE_TC>>>(edge_attr, We);                     // 3 (profiled)
    scan1_kernel<<<NB, 256>>>();                                               // 4
    scan2_kernel<<<1, 256>>>();                                                // 5
    scan3_kernel<<<(NN + 255) / 256, 256>>>();                                 // 6
    fill_kernel<<<(NE + 255) / 256, 256>>>(src, dst);                          // 7
    softagg_kernel<<<(NN + 7) / 8, 256>>>(att);                                // 8
    tail_kernel<<<296, 256, SM_TAIL>>>(x, bias, g1, bt1, W1, b1, gm, bm,
                                       W2, b2, g2, bt2, out);                  // 9
}

// round 16
// speedup vs baseline: 2.2132x; 1.0253x over previous
#include <cuda_runtime.h>
#include <cuda_bf16.h>
#include <cstdint>

typedef unsigned long long ull;

#define NN    50000
#define NE    500000
#define DIM   160
#define HEADS 5
#define MH    50
#define NV4   (DIM/4)
#define TILE  96
#define RPW   6
#define NB    ((NN + 255) / 256)
#define NCHUNK ((NN + 31) / 32)
#define HBS   162
#define TBS   52
#define W1S   162
#define W2S   54

// ---- HMMA edge GEMM constants ----
#define MT      96
#define ETHR    384
#define NTILES  ((NE + MT - 1) / MT)     // 5209
#define EAST    168                      // bf16 row stride (336B: conflict-free ldmatrix)
#define SMA_HI  0
#define SMA_LO  32256                    // 96*168*2
#define SMB_HI  64512
#define SMB_LO  118272                   // + 160*168*2
#define SM_EDGE_TC 172032

// ---------------- scratch ----------------
__device__ float g_xl[NN * DIM];
__device__ float g_xr[NN * DIM];
__device__ float g_attn[NN * DIM];
__device__ float g_ea[(size_t)NE * DIM];   // edge GEMM out, edge order (320 MB)
__device__ int   g_csrc[NE];
__device__ int   g_eid[NE];
__device__ int   g_deg[NN];
__device__ int   g_off[NN];
__device__ int   g_cur[NN];
__device__ int   g_bsum[256];

__device__ __forceinline__ float selu_f(float v) {
    const float sc = 1.0507009873554805f, al = 1.6732632423543772f;
    return v > 0.f ? sc * v : sc * al * (expf(v) - 1.f);
}

#define FFMA2(d, a, b) asm("fma.rn.f32x2 %0, %1, %2, %0;" : "+l"(d) : "l"(a), "l"(b))

__device__ __forceinline__ float unpack_add(ull v) {
    return __uint_as_float((unsigned)v) + __uint_as_float((unsigned)(v >> 32));
}

// ---------------- CSR build ----------------
__global__ void zero_deg_kernel() {
    int i = blockIdx.x * blockDim.x + threadIdx.x;
    if (i < NN) g_deg[i] = 0;
}
__global__ void count_kernel(const int* __restrict__ dst) {
    int e = blockIdx.x * blockDim.x + threadIdx.x;
    if (e < NE) atomicAdd(&g_deg[dst[e]], 1);
}
__global__ void scan1_kernel() {
    __shared__ int wsum[8];
    int tid = threadIdx.x, lane = tid & 31, warp = tid >> 5;
    int i = blockIdx.x * 256 + tid;
    int v = (i < NN) ? g_deg[i] : 0;
    int x = v;
    #pragma unroll
    for (int d = 1; d < 32; d <<= 1) {
        int y = __shfl_up_sync(0xffffffffu, x, d);
        if (lane >= d) x += y;
    }
    if (lane == 31) wsum[warp] = x;
    __syncthreads();
    if (tid == 0) {
        int s = 0;
        #pragma unroll
        for (int j = 0; j < 8; j++) { int t = wsum[j]; wsum[j] = s; s += t; }
        g_bsum[blockIdx.x] = s;
    }
    __syncthreads();
    if (i < NN) g_off[i] = x - v + wsum[warp];
}
__global__ void scan2_kernel() {
    __shared__ int wsum[8];
    int tid = threadIdx.x, lane = tid & 31, warp = tid >> 5;
    int v = (tid < NB) ? g_bsum[tid] : 0;
    int x = v;
    #pragma unroll
    for (int d = 1; d < 32; d <<= 1) {
        int y = __shfl_up_sync(0xffffffffu, x, d);
        if (lane >= d) x += y;
    }
    if (lane == 31) wsum[warp] = x;
    __syncthreads();
    if (tid == 0) {
        int s = 0;
        #pragma unroll
        for (int j = 0; j < 8; j++) { int t = wsum[j]; wsum[j] = s; s += t; }
    }
    __syncthreads();
    if (tid < NB) g_bsum[tid] = x - v + wsum[warp];
}
__global__ void scan3_kernel() {
    int i = blockIdx.x * blockDim.x + threadIdx.x;
    if (i < NN) {
        int o = g_off[i] + g_bsum[i >> 8];
        g_off[i] = o;
        g_cur[i] = o;
    }
}
__global__ void fill_kernel(const int* __restrict__ src, const int* __restrict__ dst) {
    int e = blockIdx.x * blockDim.x + threadIdx.x;
    if (e < NE) {
        int pos = atomicAdd(&g_cur[dst[e]], 1);
        g_eid[pos] = e;
        g_csrc[pos] = src[e];
    }
}

// ---------------- cp.async tile loader ----------------
__device__ __forceinline__ void tile_load_async(float* buf, const float* src_mat,
                                                long row0, long nrows, int tid) {
    unsigned base = (unsigned)__cvta_generic_to_shared(buf);
    #pragma unroll
    for (int it = 0; it < 8; it++) {
        int i = tid + it * 512;
        if (i < TILE * NV4) {
            int r = i / NV4;
            long row = row0 + r;
            const float4* p = (const float4*)src_mat +
                              (row < nrows ? row * NV4 + (i - r * NV4) : 0);
            int sz = (row < nrows) ? 16 : 0;
            asm volatile("cp.async.cg.shared.global [%0], [%1], 16, %2;\n"
                         :: "r"(base + (unsigned)i * 16u), "l"(p), "r"(sz));
        }
    }
}

// ---- f32x2 SIMT GEMM mainloop (node transform) ----
__device__ __forceinline__ void gemm_tile_f2(const float* __restrict__ Wt4,
                                             const float* __restrict__ a_s,
                                             int warp, int lane, ull acc[RPW][5]) {
    #pragma unroll
    for (int r = 0; r < RPW; r++)
        #pragma unroll
        for (int c = 0; c < 5; c++) acc[r][c] = 0ull;
    const float* arow = a_s + warp * RPW * DIM;
    const ulonglong2* wq = (const ulonglong2*)Wt4;
    #pragma unroll 2
    for (int k = 0; k < DIM; k += 4) {
        ulonglong2 xv[RPW];
        #pragma unroll
        for (int r = 0; r < RPW; r++)
            xv[r] = *(const ulonglong2*)(arow + r * DIM + k);
        ulonglong2 wv[5];
        int base = (k >> 2) * DIM + lane;
        #pragma unroll
        for (int c = 0; c < 5; c++)
            wv[c] = wq[base + 32 * c];
        #pragma unroll
        for (int r = 0; r < RPW; r++)
            #pragma unroll
            for (int c = 0; c < 5; c++) {
                FFMA2(acc[r][c], xv[r].x, wv[c].x);
                FFMA2(acc[r][c], xv[r].y, wv[c].y);
            }
    }
}

__device__ __forceinline__ void load_W_t4(float* Wt4, const float* W, int tid, int nthr) {
    for (int i = tid; i < DIM * DIM; i += nthr) {
        int kk = i / DIM, cc = i - kk * DIM;
        Wt4[(((kk >> 2) * DIM) + cc) * 4 + (kk & 3)] = W[i];
    }
}

// ---------------- K: xl = x@Wl+bl, xr = x@Wr+br ------------
__global__ __launch_bounds__(512, 1)
void node_transform_kernel(const float* __restrict__ x,
                           const float* __restrict__ Wl, const float* __restrict__ bl,
                           const float* __restrict__ Wr, const float* __restrict__ br) {
    extern __shared__ float sm[];
    float* Wt4  = sm;
    float* buf0 = sm + DIM * DIM;
    float* buf1 = buf0 + TILE * DIM;
    const float* W    = blockIdx.y ? Wr : Wl;
    const float* bias = blockIdx.y ? br : bl;
    float* out        = blockIdx.y ? g_xr : g_xl;
    int tid = threadIdx.x, lane = tid & 31, warp = tid >> 5;

    load_W_t4(Wt4, W, tid, 512);
    float bv[5];
    #pragma unroll
    for (int c = 0; c < 5; c++) bv[c] = bias[lane + 32 * c];

    int ntiles = (NN + TILE - 1) / TILE;
    float* cur = buf0; float* nxt = buf1;
    tile_load_async(cur, x, (long)blockIdx.x * TILE, NN, tid);
    asm volatile("cp.async.commit_group;\n");
    for (int t = blockIdx.x; t < ntiles; t += gridDim.x) {
        tile_load_async(nxt, x, (long)(t + gridDim.x) * TILE, NN, tid);
        asm volatile("cp.async.commit_group;\n");
        asm volatile("cp.async.wait_group 1;\n");
        __syncthreads();
        ull acc[RPW][5];
        gemm_tile_f2(Wt4, cur, warp, lane, acc);
        long r0 = (long)t * TILE + warp * RPW;
        #pragma unroll
        for (int r = 0; r < RPW; r++) {
            long gr = r0 + r;
            if (gr < NN) {
                #pragma unroll
                for (int c = 0; c < 5; c++)
                    out[gr * DIM + lane + 32 * c] = unpack_add(acc[r][c]) + bv[c];
            }
        }
        __syncthreads();
        float* tmp = cur; cur = nxt; nxt = tmp;
    }
}

// ================= HMMA (mma.sync) bf16x3-split edge GEMM =================
// Software-pipelined: registers prefetch tile t+1 fp32 data during MMA of t.
#define MMA16816(c, a, b0, b1) \
    asm volatile("mma.sync.aligned.m16n8k16.row.col.f32.bf16.bf16.f32 " \
        "{%0,%1,%2,%3}, {%4,%5,%6,%7}, {%8,%9}, {%0,%1,%2,%3};" \
        : "+f"((c)[0]), "+f"((c)[1]), "+f"((c)[2]), "+f"((c)[3]) \
        : "r"((a)[0]), "r"((a)[1]), "r"((a)[2]), "r"((a)[3]), "r"(b0), "r"(b1))

#define LDMX4(r, addr) \
    asm volatile("ldmatrix.sync.aligned.m8n8.x4.shared.b16 {%0,%1,%2,%3}, [%4];" \
        : "=r"((r)[0]), "=r"((r)[1]), "=r"((r)[2]), "=r"((r)[3]) : "r"(addr))

__global__ __launch_bounds__(ETHR, 1)
void edge_gemm_tc(const float* __restrict__ edge_attr, const float* __restrict__ We) {
    extern __shared__ char smc[];
    unsigned sbase = (unsigned)__cvta_generic_to_shared(smc);
    int tid = threadIdx.x, lane = tid & 31, wid = tid >> 5;
    int wm = wid >> 1;           // m-group: rows wm*16 .. wm*16+15 (0..5)
    int wn = wid & 1;            // n-half: cols wn*80 .. wn*80+79

    // B = We^T split: Bt[n][k] = We[k*DIM + n]
    for (int i = tid; i < DIM * DIM; i += ETHR) {
        int k = i / DIM, n = i - k * DIM;
        float v = We[i];
        __nv_bfloat16 h = __float2bfloat16(v);
        __nv_bfloat16 l = __float2bfloat16(v - __bfloat162float(h));
        unsigned off = (unsigned)(n * EAST + k) * 2u;
        *(unsigned short*)(smc + SMB_HI + off) = __bfloat16_as_ushort(h);
        *(unsigned short*)(smc + SMB_LO + off) = __bfloat16_as_ushort(l);
    }

    // ldmatrix per-lane address components
    int arow = lane & 15, akb = (lane >> 4) << 3;                 // A: m0k0/m8k0/m0k8/m8k8
    int brow = (lane & 7) + ((lane >> 4) << 3), bkb = lane & 8;   // B: n0k0/n0k8/n8k0/n8k8
    unsigned abase = sbase + (unsigned)((wm * 16 + arow) * EAST + akb) * 2u;
    unsigned bbase = sbase + (unsigned)(brow * EAST + bkb) * 2u;

    // per-thread conversion slot: 96*40=3840 float4, 10 per thread
    int crow = 0, ccol = 0;
    {
        int j0 = tid;                 // iteration stride ETHR; row/col per it computed below
        (void)j0;
    }

    float4 pf[10];
    // prologue prefetch for first tile
    {
        long eb = (long)blockIdx.x * MT;
        #pragma unroll
        for (int it = 0; it < 10; it++) {
            int j = tid + it * ETHR;
            int row = j / 40, c4 = j - row * 40;
            long rg = eb + row;
            if (rg >= NE) rg = 0;
            pf[it] = *(const float4*)(edge_attr + rg * DIM + c4 * 4);
        }
    }

    for (long t = blockIdx.x; t < NTILES; t += gridDim.x) {
        long eb = t * MT;
        // convert prefetched regs -> hi/lo bf16 smem
        #pragma unroll
        for (int it = 0; it < 10; it++) {
            int j = tid + it * ETHR;
            int row = j / 40, c4 = j - row * 40, col = c4 * 4;
            float4 v = pf[it];
            __nv_bfloat16 h0 = __float2bfloat16(v.x), h1 = __float2bfloat16(v.y);
            __nv_bfloat16 h2 = __float2bfloat16(v.z), h3 = __float2bfloat16(v.w);
            __nv_bfloat16 l0 = __float2bfloat16(v.x - __bfloat162float(h0));
            __nv_bfloat16 l1 = __float2bfloat16(v.y - __bfloat162float(h1));
            __nv_bfloat16 l2 = __float2bfloat16(v.z - __bfloat162float(h2));
            __nv_bfloat16 l3 = __float2bfloat16(v.w - __bfloat162float(h3));
            ull hp = (ull)__bfloat16_as_ushort(h0) | ((ull)__bfloat16_as_ushort(h1) << 16)
                   | ((ull)__bfloat16_as_ushort(h2) << 32) | ((ull)__bfloat16_as_ushort(h3) << 48);
            ull lp = (ull)__bfloat16_as_ushort(l0) | ((ull)__bfloat16_as_ushort(l1) << 16)
                   | ((ull)__bfloat16_as_ushort(l2) << 32) | ((ull)__bfloat16_as_ushort(l3) << 48);
            unsigned off = (unsigned)(row * EAST + col) * 2u;
            *(ull*)(smc + SMA_HI + off) = hp;
            *(ull*)(smc + SMA_LO + off) = lp;
        }
        __syncthreads();

        // prefetch next tile's fp32 data (hidden under MMA below)
        {
            long tn = t + gridDim.x;
            long ebn = tn * MT;
            bool valid = (tn < NTILES);
            #pragma unroll
            for (int it = 0; it < 10; it++) {
                int j = tid + it * ETHR;
                int row = j / 40, c4 = j - row * 40;
                long rg = valid ? (ebn + row) : 0;
                if (rg >= NE) rg = 0;
                pf[it] = *(const float4*)(edge_attr + rg * DIM + c4 * 4);
            }
        }

        float c[10][4];
        #pragma unroll
        for (int j = 0; j < 10; j++)
            #pragma unroll
            for (int q = 0; q < 4; q++) c[j][q] = 0.f;

        #pragma unroll
        for (int kc = 0; kc < 10; kc++) {
            unsigned k2 = (unsigned)(kc * 16) * 2u;
            unsigned ah[4], al[4];
            LDMX4(ah, abase + SMA_HI + k2);
            LDMX4(al, abase + SMA_LO + k2);
            #pragma unroll
            for (int jp = 0; jp < 5; jp++) {
                unsigned noff = (unsigned)((wn * 80 + jp * 16) * EAST) * 2u;
                unsigned bh[4], bl[4];
                LDMX4(bh, bbase + SMB_HI + noff + k2);
                LDMX4(bl, bbase + SMB_LO + noff + k2);
                int j0 = jp * 2, j1 = j0 + 1;
                MMA16816(c[j0], ah, bh[0], bh[1]);
                MMA16816(c[j1], ah, bh[2], bh[3]);
                MMA16816(c[j0], al, bh[0], bh[1]);
                MMA16816(c[j1], al, bh[2], bh[3]);
                MMA16816(c[j0], ah, bl[0], bl[1]);
                MMA16816(c[j1], ah, bl[2], bl[3]);
            }
        }

        // epilogue: coalesced edge-order stores
        long e1 = eb + wm * 16 + (lane >> 2);
        long e2 = e1 + 8;
        int ncol = wn * 80 + 2 * (lane & 3);
        #pragma unroll
        for (int j = 0; j < 10; j++) {
            int n = ncol + j * 8;
            if (e1 < NE) *(float2*)(g_ea + (size_t)e1 * DIM + n) = make_float2(c[j][0], c[j][1]);
            if (e2 < NE) *(float2*)(g_ea + (size_t)e2 * DIM + n) = make_float2(c[j][2], c[j][3]);
        }
        __syncthreads();
    }
}

// ---- fused score + softmax + aggregate (warp per node; ea via eid gather) --
__global__ __launch_bounds__(256)
void softagg_kernel(const float* __restrict__ att) {
    __shared__ float att_s[DIM];
    int tid = threadIdx.x;
    if (tid < DIM) att_s[tid] = att[tid];
    __syncthreads();
    int w = (int)(((long)blockIdx.x * blockDim.x + tid) >> 5);
    int lane = tid & 31;
    if (w >= NN) return;
    long off = g_off[w]; int deg = g_deg[w];
    const float* xrr = g_xr + (long)w * DIM + lane;
    float xr0 = xrr[0], xr1 = xrr[32], xr2 = xrr[64], xr3 = xrr[96], xr4 = xrr[128];
    float av0 = att_s[lane],      av1 = att_s[lane + 32], av2 = att_s[lane + 64],
          av3 = att_s[lane + 96], av4 = att_s[lane + 128];
    float a0 = 0.f, a1 = 0.f, a2 = 0.f, a3 = 0.f, a4 = 0.f;
    float s0 = 0.f, s1 = 0.f, s2 = 0.f, s3 = 0.f, s4 = 0.f;
    const int* sp = g_csrc + off;
    const int* ep = g_eid + off;
    #pragma unroll 2
    for (int i = 0; i < deg; i++) {
        long e = ep[i];                                          // broadcast
        const float* ear = g_ea + (size_t)e * DIM + lane;
        int s = sp[i];                                           // broadcast
        const float* xlr = g_xl + (long)s * DIM + lane;
        float xl0 = xlr[0], xl1 = xlr[32], xl2 = xlr[64], xl3 = xlr[96], xl4 = xlr[128];
        float m0 = __ldcs(ear)       + xl0 + xr0;
        float m1 = __ldcs(ear + 32)  + xl1 + xr1;
        float m2 = __ldcs(ear + 64)  + xl2 + xr2;
        float m3 = __ldcs(ear + 96)  + xl3 + xr3;
        float m4 = __ldcs(ear + 128) + xl4 + xr4;
        m0 = (m0 > 0.f) ? m0 : 0.2f * m0;
        m1 = (m1 > 0.f) ? m1 : 0.2f * m1;
        m2 = (m2 > 0.f) ? m2 : 0.2f * m2;
        m3 = (m3 > 0.f) ? m3 : 0.2f * m3;
        m4 = (m4 > 0.f) ? m4 : 0.2f * m4;
        float p0 = m0 * av0, p1 = m1 * av1, p2 = m2 * av2, p3 = m3 * av3, p4 = m4 * av4;
        #pragma unroll
        for (int o = 16; o; o >>= 1) {
            p0 += __shfl_xor_sync(0xffffffffu, p0, o);
            p1 += __shfl_xor_sync(0xffffffffu, p1, o);
            p2 += __shfl_xor_sync(0xffffffffu, p2, o);
            p3 += __shfl_xor_sync(0xffffffffu, p3, o);
            p4 += __shfl_xor_sync(0xffffffffu, p4, o);
        }
        float w0 = __expf(p0), w1 = __expf(p1), w2 = __expf(p2);
        float w3 = __expf(p3), w4 = __expf(p4);
        s0 += w0; s1 += w1; s2 += w2; s3 += w3; s4 += w4;
        a0 = fmaf(w0, xl0, a0);
        a1 = fmaf(w1, xl1, a1);
        a2 = fmaf(w2, xl2, a2);
        a3 = fmaf(w3, xl3, a3);
        a4 = fmaf(w4, xl4, a4);
    }
    float* o = g_attn + (long)w * DIM + lane;
    if (deg > 0) {
        o[0]   = a0 / s0;
        o[32]  = a1 / s1;
        o[64]  = a2 / s2;
        o[96]  = a3 / s3;
        o[128] = a4 / s4;
    } else {
        o[0] = 0.f; o[32] = 0.f; o[64] = 0.f; o[96] = 0.f; o[128] = 0.f;
    }
}

// ------- fused tail: LN1 -> MLP(160->50->160) -> LN2, FFMA2 GEMMs ----------
__global__ __launch_bounds__(256, 2)
void tail_kernel(const float* __restrict__ x, const float* __restrict__ bias,
                 const float* __restrict__ g1, const float* __restrict__ bt1,
                 const float* __restrict__ W1, const float* __restrict__ b1,
                 const float* __restrict__ gm, const float* __restrict__ bm,
                 const float* __restrict__ W2, const float* __restrict__ b2,
                 const float* __restrict__ g2, const float* __restrict__ bt2,
                 float* __restrict__ out) {
    extern __shared__ float sm[];
    float* W1t   = sm;
    float* W2t   = W1t + MH * W1S;
    float* hbuf  = W2t + DIM * W2S;
    float* tbuf  = hbuf + 32 * HBS;
    float* bias_s = tbuf + 32 * TBS;
    float* g1_s  = bias_s + DIM;
    float* bt1_s = g1_s + DIM;
    float* b2_s  = bt1_s + DIM;
    float* g2_s  = b2_s + DIM;
    float* bt2_s = g2_s + DIM;
    float* b1_s  = bt2_s + DIM;
    float* gm_s  = b1_s + MH;
    float* bm_s  = gm_s + MH;
    int tid = threadIdx.x, lane = tid & 31, warp = tid >> 5;

    for (int i = tid; i < DIM * MH; i += 256) {
        int kk = i / MH, cc = i - kk * MH;
        W1t[cc * W1S + kk] = W1[i];
    }
    for (int i = tid; i < MH * DIM; i += 256) {
        int kk = i / DIM, cc = i - kk * DIM;
        W2t[cc * W2S + kk] = W2[i];
    }
    if (tid < DIM) {
        bias_s[tid] = bias[tid]; g1_s[tid] = g1[tid]; bt1_s[tid] = bt1[tid];
        b2_s[tid] = b2[tid]; g2_s[tid] = g2[tid]; bt2_s[tid] = bt2[tid];
    }
    if (tid < MH) { b1_s[tid] = b1[tid]; gm_s[tid] = gm[tid]; bm_s[tid] = bm[tid]; }
    __syncthreads();

    for (int chunk = blockIdx.x; chunk < NCHUNK; chunk += gridDim.x) {
        int n0 = chunk * 32;
        #pragma unroll
        for (int i = 0; i < 4; i++) {
            int nl = warp + 8 * i;
            long n = n0 + nl;
            float v[5];
            if (n < NN) {
                #pragma unroll
                for (int c = 0; c < 5; c++) {
                    int col = lane + 32 * c;
                    v[c] = x[n * DIM + col] + g_attn[n * DIM + col] + bias_s[col];
                }
            } else {
                #pragma unroll
                for (int c = 0; c < 5; c++) v[c] = 0.f;
            }
            float p1 = 0.f, p2 = 0.f;
            #pragma unroll
            for (int c = 0; c < 5; c++) { p1 += v[c]; p2 += v[c] * v[c]; }
            #pragma unroll
            for (int off = 16; off; off >>= 1) {
                p1 += __shfl_xor_sync(0xffffffffu, p1, off);
                p2 += __shfl_xor_sync(0xffffffffu, p2, off);
            }
            float mu = p1 * (1.f / DIM);
            float rstd = rsqrtf(p2 * (1.f / DIM) - mu * mu + 1e-5f);
            #pragma unroll
            for (int c = 0; c < 5; c++) {
                int col = lane + 32 * c;
                hbuf[nl * HBS + col] = (v[c] - mu) * rstd * g1_s[col] + bt1_s[col];
            }
        }
        __syncthreads();
        {
            int cg = lane, ng = warp;
            ull a0[4] = {0ull,0ull,0ull,0ull}, a1[4] = {0ull,0ull,0ull,0ull};
            #pragma unroll 4
            for (int k = 0; k < DIM; k += 2) {
                ull w0 = *(const ull*)(W1t + cg * W1S + k);
                ull w1 = (cg < MH - 32) ? *(const ull*)(W1t + (cg + 32) * W1S + k) : 0ull;
                #pragma unroll
                for (int i = 0; i < 4; i++) {
                    ull hv = *(const ull*)(hbuf + (ng * 4 + i) * HBS + k);
                    FFMA2(a0[i], hv, w0);
                    FFMA2(a1[i], hv, w1);
                }
            }
            #pragma unroll
            for (int i = 0; i < 4; i++) {
                int nl = ng * 4 + i;
                tbuf[nl * TBS + cg] = selu_f(unpack_add(a0[i]) + b1_s[cg]);
                if (cg < MH - 32)
                    tbuf[nl * TBS + cg + 32] = selu_f(unpack_add(a1[i]) + b1_s[cg + 32]);
            }
        }
        __syncthreads();
        if (tid < 32) {
            float p1 = 0.f, p2 = 0.f;
            for (int k = 0; k < MH; k++) { float t = tbuf[tid * TBS + k]; p1 += t; p2 += t * t; }
            float mu = p1 * (1.f / MH);
            float rstd = rsqrtf(p2 * (1.f / MH) - mu * mu + 1e-5f);
            for (int k = 0; k < MH; k++)
                tbuf[tid * TBS + k] = (tbuf[tid * TBS + k] - mu) * rstd * gm_s[k] + bm_s[k];
        }
        __syncthreads();
        {
            ull acc[4][5];
            #pragma unroll
            for (int i = 0; i < 4; i++)
                #pragma unroll
                for (int c = 0; c < 5; c++) acc[i][c] = 0ull;
            #pragma unroll 5
            for (int k = 0; k < MH; k += 2) {
                ull wv[5];
                #pragma unroll
                for (int c = 0; c < 5; c++)
                    wv[c] = *(const ull*)(W2t + (lane + 32 * c) * W2S + k);
                #pragma unroll
                for (int i = 0; i < 4; i++) {
                    ull uv = *(const ull*)(tbuf + (warp * 4 + i) * TBS + k);
                    #pragma unroll
                    for (int c = 0; c < 5; c++) FFMA2(acc[i][c], uv, wv[c]);
                }
            }
            #pragma unroll
            for (int i = 0; i < 4; i++) {
                int nl = warp * 4 + i;
                long n = n0 + nl;
                float v[5];
                #pragma unroll
                for (int c = 0; c < 5; c++) {
                    int col = lane + 32 * c;
                    v[c] = hbuf[nl * HBS + col] + unpack_add(acc[i][c]) + b2_s[col];
                }
                float p1 = 0.f, p2 = 0.f;
                #pragma unroll
                for (int c = 0; c < 5; c++) { p1 += v[c]; p2 += v[c] * v[c]; }
                #pragma unroll
                for (int off = 16; off; off >>= 1) {
                    p1 += __shfl_xor_sync(0xffffffffu, p1, off);
                    p2 += __shfl_xor_sync(0xffffffffu, p2, off);
                }
                float mu = p1 * (1.f / DIM);
                float rstd = rsqrtf(p2 * (1.f / DIM) - mu * mu + 1e-5f);
                if (n < NN) {
                    #pragma unroll
                    for (int c = 0; c < 5; c++) {
                        int col = lane + 32 * c;
                        out[n * DIM + col] = (v[c] - mu) * rstd * g2_s[col] + bt2_s[col];
                    }
                }
            }
        }
        __syncthreads();
    }
}

// ---------------- launch ----------------
extern "C" void kernel_launch(void* const* d_in, const int* in_sizes, int n_in,
                              void* d_out, int out_size) {
    const float* x         = (const float*)d_in[0];
    const int*   edge_index= (const int*)d_in[1];
    const float* edge_attr = (const float*)d_in[2];
    const float* Wl  = (const float*)d_in[5];
    const float* bl  = (const float*)d_in[6];
    const float* Wr  = (const float*)d_in[7];
    const float* br  = (const float*)d_in[8];
    const float* We  = (const float*)d_in[9];
    const float* att = (const float*)d_in[10];
    const float* bias= (const float*)d_in[11];
    const float* g1  = (const float*)d_in[12];
    const float* bt1 = (const float*)d_in[13];
    const float* W1  = (const float*)d_in[14];
    const float* b1  = (const float*)d_in[15];
    const float* gm  = (const float*)d_in[16];
    const float* bm  = (const float*)d_in[17];
    const float* W2  = (const float*)d_in[18];
    const float* b2  = (const float*)d_in[19];
    const float* g2  = (const float*)d_in[20];
    const float* bt2 = (const float*)d_in[21];
    float* out = (float*)d_out;
    const int* src = edge_index;
    const int* dst = edge_index + NE;

    const int SM_GEMM = (DIM * DIM + 2 * TILE * DIM) * (int)sizeof(float);
    const int SM_TAIL = (MH * W1S + DIM * W2S + 32 * HBS + 32 * TBS + 6 * DIM + 3 * MH)
                        * (int)sizeof(float);
    cudaFuncSetAttribute(node_transform_kernel, cudaFuncAttributeMaxDynamicSharedMemorySize, SM_GEMM);
    cudaFuncSetAttribute(edge_gemm_tc,          cudaFuncAttributeMaxDynamicSharedMemorySize, SM_EDGE_TC);
    cudaFuncSetAttribute(tail_kernel,           cudaFuncAttributeMaxDynamicSharedMemorySize, SM_TAIL);

    node_transform_kernel<<<dim3(148, 2), 512, SM_GEMM>>>(x, Wl, bl, Wr, br);  // 0
    zero_deg_kernel<<<(NN + 255) / 256, 256>>>();                              // 1
    count_kernel<<<(NE + 255) / 256, 256>>>(dst);                              // 2
    edge_gemm_tc<<<148, ETHR, SM_EDGE_TC>>>(edge_attr, We);                    // 3 (profiled)
    scan1_kernel<<<NB, 256>>>();                                               // 4
    scan2_kernel<<<1, 256>>>();                                                // 5
    scan3_kernel<<<(NN + 255) / 256, 256>>>();                                 // 6
    fill_kernel<<<(NE + 255) / 256, 256>>>(src, dst);                          // 7
    softagg_kernel<<<(NN + 7) / 8, 256>>>(att);                                // 8
    tail_kernel<<<296, 256, SM_TAIL>>>(x, bias, g1, bt1, W1, b1, gm, bm,
                                       W2, b2, g2, bt2, out);                  // 9
}